// round 1
// baseline (speedup 1.0000x reference)
#include <cuda_runtime.h>
#include <math.h>

#define NB 1024
#define ND 256
#define NR 16384
#define NW 64
#define NSPLIT 16
#define EPSF 1e-16f

// ---------------- scratch (no allocations allowed) ----------------
__device__ float g_sim[(size_t)NB * NR];   // beta*sim logits, then a (in place)
__device__ float g_pl [(size_t)NB * NR];   // p logits, then p (in place)
__device__ float g_v  [NB * NW];
__device__ float g_vn [NB];
__device__ float g_beta[NB];
__device__ float g_gamma[NB];
__device__ float g_mn [NR];
__device__ float g_mem2[NR * NW];
__device__ float g_part[NSPLIT * NB * NW];

__device__ __forceinline__ float softplus_f(float z) {
    return z > 0.f ? z + log1pf(expf(-z)) : log1pf(expf(z));
}

// ---------------- K1: controller heads: v, |v|, beta, gamma ----------------
__global__ void heads_kernel(const float* __restrict__ x,
                             const float* __restrict__ Wv, const float* __restrict__ bv,
                             const float* __restrict__ Wb, const float* __restrict__ bb,
                             const float* __restrict__ Wg, const float* __restrict__ bg) {
    int b = blockIdx.x, t = threadIdx.x;        // 64 threads
    __shared__ float xs[ND];
    __shared__ float red[64];
    for (int i = t; i < ND; i += 64) xs[i] = x[b * ND + i];
    __syncthreads();

    float acc = 0.f;
    #pragma unroll 8
    for (int d = 0; d < ND; ++d) acc = fmaf(xs[d], Wv[d * NW + t], acc);
    float pb = 0.f, pg = 0.f;
    for (int d = t; d < ND; d += 64) {
        pb = fmaf(xs[d], Wb[d], pb);
        pg = fmaf(xs[d], Wg[d], pg);
    }
    float v = acc + bv[t];
    g_v[b * NW + t] = v;

    red[t] = v * v; __syncthreads();
    for (int s = 32; s > 0; s >>= 1) { if (t < s) red[t] += red[t + s]; __syncthreads(); }
    if (t == 0) g_vn[b] = sqrtf(red[0]);
    __syncthreads();

    red[t] = pb; __syncthreads();
    for (int s = 32; s > 0; s >>= 1) { if (t < s) red[t] += red[t + s]; __syncthreads(); }
    if (t == 0) g_beta[b] = softplus_f(red[0] + bb[0]);
    __syncthreads();

    red[t] = pg; __syncthreads();
    for (int s = 32; s > 0; s >>= 1) { if (t < s) red[t] += red[t + s]; __syncthreads(); }
    if (t == 0) g_gamma[b] = 1.f + softplus_f(red[0] + bg[0]);
}

// ---------------- K0: memory row norms ----------------
__global__ void mn_kernel(const float* __restrict__ mem) {
    int r = blockIdx.x * blockDim.x + threadIdx.x;
    if (r >= NR) return;
    const float4* m4 = (const float4*)(mem + (size_t)r * NW);
    float s = 0.f;
    #pragma unroll
    for (int i = 0; i < NW / 4; ++i) {
        float4 t4 = m4[i];
        s += t4.x * t4.x + t4.y * t4.y + t4.z * t4.z + t4.w * t4.w;
    }
    g_mn[r] = sqrtf(s);
}

// ---------------- K2: sim logits = beta * (v . mem_r) / (vn*mn + eps) ----------------
// 64x64 tile, K=64 fully in smem. NT layout (both operands K-contiguous).
__global__ void sim_gemm(const float* __restrict__ mem) {
    __shared__ float As[64][68];   // As[k][bi] = v[b0+bi][k]
    __shared__ float Bs[64][68];   // Bs[k][rj] = mem[r0+rj][k]
    int r0 = blockIdx.x * 64, b0 = blockIdx.y * 64;
    int tid = threadIdx.x;
    int tx = tid & 15, ty = tid >> 4;

    #pragma unroll
    for (int m = 0; m < 4; ++m) {
        int q = tid + m * 256;           // 0..1023 float4 slots
        int row = q >> 4;                // 0..63
        int k4  = (q & 15) << 2;         // 0..60
        float4 a4 = *(const float4*)&g_v[(b0 + row) * NW + k4];
        As[k4 + 0][row] = a4.x; As[k4 + 1][row] = a4.y;
        As[k4 + 2][row] = a4.z; As[k4 + 3][row] = a4.w;
        float4 b4 = *(const float4*)&mem[(size_t)(r0 + row) * NW + k4];
        Bs[k4 + 0][row] = b4.x; Bs[k4 + 1][row] = b4.y;
        Bs[k4 + 2][row] = b4.z; Bs[k4 + 3][row] = b4.w;
    }
    __syncthreads();

    float acc[4][4] = {};
    #pragma unroll
    for (int k = 0; k < 64; ++k) {
        float4 ra = *(float4*)&As[k][ty * 4];
        float4 rb = *(float4*)&Bs[k][tx * 4];
        float a_[4] = {ra.x, ra.y, ra.z, ra.w};
        float b_[4] = {rb.x, rb.y, rb.z, rb.w};
        #pragma unroll
        for (int i = 0; i < 4; ++i)
            #pragma unroll
            for (int j = 0; j < 4; ++j)
                acc[i][j] = fmaf(a_[i], b_[j], acc[i][j]);
    }

    #pragma unroll
    for (int i = 0; i < 4; ++i) {
        int b = b0 + ty * 4 + i;
        float be = g_beta[b], vn = g_vn[b];
        #pragma unroll
        for (int j = 0; j < 4; ++j) {
            int r = r0 + tx * 4 + j;
            g_sim[(size_t)b * NR + r] = be * acc[i][j] / (vn * g_mn[r] + EPSF);
        }
    }
}

// ---------------- K3: softmax -> conv(K=3,'SAME') -> pow(gamma) -> renorm ----------------
__global__ void wa_kernel(const float* __restrict__ conv_k, const float* __restrict__ conv_b) {
    extern __shared__ float sm[];
    float* ws = sm;            // 16384 (exp values)
    float* as = sm + NR;       // 16384 (sharpened)
    __shared__ float red[256];
    int b = blockIdx.x, t = threadIdx.x;
    float* row = g_sim + (size_t)b * NR;

    float mx = -1e30f;
    for (int r = t; r < NR; r += 256) { float l = row[r]; ws[r] = l; mx = fmaxf(mx, l); }
    red[t] = mx; __syncthreads();
    for (int s = 128; s > 0; s >>= 1) { if (t < s) red[t] = fmaxf(red[t], red[t + s]); __syncthreads(); }
    mx = red[0];

    float sum = 0.f;
    for (int r = t; r < NR; r += 256) { float e = __expf(ws[r] - mx); ws[r] = e; sum += e; }
    __syncthreads();
    red[t] = sum; __syncthreads();
    for (int s = 128; s > 0; s >>= 1) { if (t < s) red[t] += red[t + s]; __syncthreads(); }
    float inv = 1.f / red[0];

    float c0 = conv_k[0], c1 = conv_k[1], c2 = conv_k[2], cb = conv_b[0];
    float gam = g_gamma[b];
    float asum = 0.f;
    for (int r = t; r < NR; r += 256) {
        float wl = (r > 0)      ? ws[r - 1] : 0.f;
        float wr = (r < NR - 1) ? ws[r + 1] : 0.f;
        float wc = fmaf(wl, c0, fmaf(ws[r], c1, wr * c2)) * inv + cb;
        float a = powf(wc, gam);
        as[r] = a; asum += a;
    }
    __syncthreads();
    red[t] = asum; __syncthreads();
    for (int s = 128; s > 0; s >>= 1) { if (t < s) red[t] += red[t + s]; __syncthreads(); }
    float invd = 1.f / (red[0] + (float)NR * EPSF);

    for (int r = t; r < NR; r += 256) row[r] = as[r] * invd;
}

// ---------------- K4: erase/add + mem2 (TN GEMM, C[r][w] = sum_b a[b][r] v[b][w]) ----------------
__global__ void add_gemm(const float* __restrict__ mem) {
    __shared__ float As[16][68];   // As[kk][ri] = a[k0+kk][r0+ri]
    __shared__ float Bs[16][68];   // Bs[kk][w ] = v[k0+kk][w]
    int r0 = blockIdx.x * 64;
    int tid = threadIdx.x, tx = tid & 15, ty = tid >> 4;
    float acc[4][4] = {};
    float er[4] = {};

    for (int k0 = 0; k0 < NB; k0 += 16) {
        int kk = tid >> 4, c4 = (tid & 15) << 2;
        *(float4*)&As[kk][c4] = *(const float4*)&g_sim[(size_t)(k0 + kk) * NR + r0 + c4];
        *(float4*)&Bs[kk][c4] = *(const float4*)&g_v[(k0 + kk) * NW + c4];
        __syncthreads();
        #pragma unroll
        for (int k = 0; k < 16; ++k) {
            float4 ra = *(float4*)&As[k][ty * 4];
            float4 rb = *(float4*)&Bs[k][tx * 4];
            float a_[4] = {ra.x, ra.y, ra.z, ra.w};
            float b_[4] = {rb.x, rb.y, rb.z, rb.w};
            er[0] += a_[0]; er[1] += a_[1]; er[2] += a_[2]; er[3] += a_[3];
            #pragma unroll
            for (int i = 0; i < 4; ++i)
                #pragma unroll
                for (int j = 0; j < 4; ++j)
                    acc[i][j] = fmaf(a_[i], b_[j], acc[i][j]);
        }
        __syncthreads();
    }
    const float invB = 1.f / (float)NB;
    #pragma unroll
    for (int i = 0; i < 4; ++i) {
        int r = r0 + ty * 4 + i;
        float e = er[i] * invB;
        #pragma unroll
        for (int j = 0; j < 4; ++j) {
            int w = tx * 4 + j;
            g_mem2[r * NW + w] = mem[(size_t)r * NW + w] * (1.f - e) + acc[i][j] * invB;
        }
    }
}

// ---------------- K5: p logits = x @ Wp + bp (128x128x8 fp32 tile) ----------------
__global__ void pl_gemm(const float* __restrict__ x, const float* __restrict__ Wp,
                        const float* __restrict__ bp) {
    __shared__ float As[8][132];   // As[k][bi]
    __shared__ float Bs[8][132];   // Bs[k][rj]
    int r0 = blockIdx.x * 128, b0 = blockIdx.y * 128;
    int tid = threadIdx.x;
    int tx = tid & 15, ty = tid >> 4;
    float acc[8][8] = {};

    for (int k0 = 0; k0 < ND; k0 += 8) {
        {   // A: x[(b0+row)][k0+kk], transpose into smem
            int row = tid >> 1;
            int kk  = (tid & 1) << 2;
            float4 a4 = *(const float4*)&x[(size_t)(b0 + row) * ND + k0 + kk];
            As[kk + 0][row] = a4.x; As[kk + 1][row] = a4.y;
            As[kk + 2][row] = a4.z; As[kk + 3][row] = a4.w;
        }
        {   // B: Wp[(k0+kk)][r0+col], direct
            int kk  = tid >> 5;
            int col = (tid & 31) << 2;
            *(float4*)&Bs[kk][col] = *(const float4*)&Wp[(size_t)(k0 + kk) * NR + r0 + col];
        }
        __syncthreads();
        #pragma unroll
        for (int k = 0; k < 8; ++k) {
            float ra[8], rb[8];
            *(float4*)&ra[0] = *(float4*)&As[k][ty * 4];
            *(float4*)&ra[4] = *(float4*)&As[k][64 + ty * 4];
            *(float4*)&rb[0] = *(float4*)&Bs[k][tx * 4];
            *(float4*)&rb[4] = *(float4*)&Bs[k][64 + tx * 4];
            #pragma unroll
            for (int i = 0; i < 8; ++i)
                #pragma unroll
                for (int j = 0; j < 8; ++j)
                    acc[i][j] = fmaf(ra[i], rb[j], acc[i][j]);
        }
        __syncthreads();
    }

    #pragma unroll
    for (int i = 0; i < 8; ++i) {
        int b = b0 + (i < 4 ? ty * 4 + i : 64 + ty * 4 + (i - 4));
        #pragma unroll
        for (int j = 0; j < 8; ++j) {
            int r = r0 + (j < 4 ? tx * 4 + j : 64 + tx * 4 + (j - 4));
            g_pl[(size_t)b * NR + r] = acc[i][j] + bp[r];
        }
    }
}

// ---------------- K6: row softmax for p ----------------
__global__ void psm_kernel() {
    extern __shared__ float ws[];
    __shared__ float red[256];
    int b = blockIdx.x, t = threadIdx.x;
    float* row = g_pl + (size_t)b * NR;

    float mx = -1e30f;
    for (int r = t; r < NR; r += 256) { float l = row[r]; ws[r] = l; mx = fmaxf(mx, l); }
    red[t] = mx; __syncthreads();
    for (int s = 128; s > 0; s >>= 1) { if (t < s) red[t] = fmaxf(red[t], red[t + s]); __syncthreads(); }
    mx = red[0];

    float sum = 0.f;
    for (int r = t; r < NR; r += 256) { float e = __expf(ws[r] - mx); ws[r] = e; sum += e; }
    __syncthreads();
    red[t] = sum; __syncthreads();
    for (int s = 128; s > 0; s >>= 1) { if (t < s) red[t] += red[t + s]; __syncthreads(); }
    float inv = 1.f / red[0];

    for (int r = t; r < NR; r += 256) row[r] = ws[r] * inv;
}

// ---------------- K7a: out = p @ mem2, split-K=16, deterministic partials ----------------
__global__ void out_gemm() {
    __shared__ float As[16][68];   // As[kk][bi] = p[b0+bi][k0+kk]
    __shared__ float Bs[16][68];   // Bs[kk][w]  = mem2[k0+kk][w]
    int split = blockIdx.x;                 // 0..15
    int b0 = blockIdx.y * 64;
    int kbase = split * (NR / NSPLIT);      // 1024 per split
    int tid = threadIdx.x, tx = tid & 15, ty = tid >> 4;
    float acc[4][4] = {};

    for (int k0 = kbase; k0 < kbase + NR / NSPLIT; k0 += 16) {
        {
            int i = tid >> 2, kq = (tid & 3) << 2;
            float4 a4 = *(const float4*)&g_pl[(size_t)(b0 + i) * NR + k0 + kq];
            As[kq + 0][i] = a4.x; As[kq + 1][i] = a4.y;
            As[kq + 2][i] = a4.z; As[kq + 3][i] = a4.w;
        }
        {
            int kk = tid >> 4, c4 = (tid & 15) << 2;
            *(float4*)&Bs[kk][c4] = *(const float4*)&g_mem2[(k0 + kk) * NW + c4];
        }
        __syncthreads();
        #pragma unroll
        for (int k = 0; k < 16; ++k) {
            float4 ra = *(float4*)&As[k][ty * 4];
            float4 rb = *(float4*)&Bs[k][tx * 4];
            float a_[4] = {ra.x, ra.y, ra.z, ra.w};
            float b_[4] = {rb.x, rb.y, rb.z, rb.w};
            #pragma unroll
            for (int i = 0; i < 4; ++i)
                #pragma unroll
                for (int j = 0; j < 4; ++j)
                    acc[i][j] = fmaf(a_[i], b_[j], acc[i][j]);
        }
        __syncthreads();
    }
    #pragma unroll
    for (int i = 0; i < 4; ++i)
        #pragma unroll
        for (int j = 0; j < 4; ++j)
            g_part[(size_t)split * (NB * NW) + (b0 + ty * 4 + i) * NW + tx * 4 + j] = acc[i][j];
}

__global__ void out_reduce(float* __restrict__ out) {
    int i = blockIdx.x * blockDim.x + threadIdx.x;
    float s = 0.f;
    #pragma unroll
    for (int p = 0; p < NSPLIT; ++p) s += g_part[(size_t)p * (NB * NW) + i];
    out[i] = s;
}

// ---------------- launch ----------------
extern "C" void kernel_launch(void* const* d_in, const int* in_sizes, int n_in,
                              void* d_out, int out_size) {
    const float* x   = (const float*)d_in[0];
    const float* Wv  = (const float*)d_in[1];
    const float* bv  = (const float*)d_in[2];
    const float* Wb  = (const float*)d_in[3];
    const float* bb  = (const float*)d_in[4];
    const float* Wg  = (const float*)d_in[5];
    const float* bg  = (const float*)d_in[6];
    const float* Wp  = (const float*)d_in[7];
    const float* bp  = (const float*)d_in[8];
    const float* ck  = (const float*)d_in[9];
    const float* cbv = (const float*)d_in[10];
    const float* mem = (const float*)d_in[11];
    float* out = (float*)d_out;
    (void)in_sizes; (void)n_in; (void)out_size;

    cudaFuncSetAttribute(wa_kernel,  cudaFuncAttributeMaxDynamicSharedMemorySize, 2 * NR * 4);
    cudaFuncSetAttribute(psm_kernel, cudaFuncAttributeMaxDynamicSharedMemorySize, NR * 4);

    heads_kernel<<<NB, 64>>>(x, Wv, bv, Wb, bb, Wg, bg);
    mn_kernel<<<NR / 256, 256>>>(mem);
    sim_gemm<<<dim3(NR / 64, NB / 64), 256>>>(mem);
    wa_kernel<<<NB, 256, 2 * NR * 4>>>(ck, cbv);
    add_gemm<<<NR / 64, 256>>>(mem);
    pl_gemm<<<dim3(NR / 128, NB / 128), 256>>>(x, Wp, bp);
    psm_kernel<<<NB, 256, NR * 4>>>();
    out_gemm<<<dim3(NSPLIT, NB / 64), 256>>>();
    out_reduce<<<NB * NW / 256, 256>>>(out);
}

// round 2
// speedup vs baseline: 1.2741x; 1.2741x over previous
#include <cuda_runtime.h>
#include <math.h>

#define NB 1024
#define ND 256
#define NR 16384
#define NW 64
#define NSPLIT 16
#define EPSF 1e-16f

// ---------------- scratch (no allocations allowed) ----------------
__device__ float g_sim[(size_t)NB * NR];   // beta*sim logits, then a (in place)
__device__ float g_pl [(size_t)NB * NR];   // p logits (raw; exp fused into out_gemm)
__device__ float g_v  [NB * NW];
__device__ float g_vn [NB];
__device__ float g_beta[NB];
__device__ float g_gamma[NB];
__device__ float g_mn [NR];
__device__ float g_mem2[NR * NW];
__device__ float g_part[NSPLIT * NB * NW];
__device__ float g_pmx [NB];
__device__ float g_pinv[NB];

__device__ __forceinline__ float softplus_f(float z) {
    return z > 0.f ? z + log1pf(expf(-z)) : log1pf(expf(z));
}

// block reductions for 1024 threads (32 warps)
__device__ __forceinline__ float blk_max(float v, float* red) {
    int lane = threadIdx.x & 31, w = threadIdx.x >> 5;
    #pragma unroll
    for (int o = 16; o; o >>= 1) v = fmaxf(v, __shfl_xor_sync(0xffffffffu, v, o));
    if (!lane) red[w] = v;
    __syncthreads();
    if (w == 0) {
        v = red[lane];
        #pragma unroll
        for (int o = 16; o; o >>= 1) v = fmaxf(v, __shfl_xor_sync(0xffffffffu, v, o));
        if (!lane) red[0] = v;
    }
    __syncthreads();
    v = red[0];
    __syncthreads();
    return v;
}
__device__ __forceinline__ float blk_sum(float v, float* red) {
    int lane = threadIdx.x & 31, w = threadIdx.x >> 5;
    #pragma unroll
    for (int o = 16; o; o >>= 1) v += __shfl_xor_sync(0xffffffffu, v, o);
    if (!lane) red[w] = v;
    __syncthreads();
    if (w == 0) {
        v = red[lane];
        #pragma unroll
        for (int o = 16; o; o >>= 1) v += __shfl_xor_sync(0xffffffffu, v, o);
        if (!lane) red[0] = v;
    }
    __syncthreads();
    v = red[0];
    __syncthreads();
    return v;
}

// ---------------- K1: controller heads: v, |v|, beta, gamma ----------------
__global__ void heads_kernel(const float* __restrict__ x,
                             const float* __restrict__ Wv, const float* __restrict__ bv,
                             const float* __restrict__ Wb, const float* __restrict__ bb,
                             const float* __restrict__ Wg, const float* __restrict__ bg) {
    int b = blockIdx.x, t = threadIdx.x;        // 64 threads
    __shared__ float xs[ND];
    __shared__ float red[64];
    for (int i = t; i < ND; i += 64) xs[i] = x[b * ND + i];
    __syncthreads();

    float acc = 0.f;
    #pragma unroll 8
    for (int d = 0; d < ND; ++d) acc = fmaf(xs[d], Wv[d * NW + t], acc);
    float pb = 0.f, pg = 0.f;
    for (int d = t; d < ND; d += 64) {
        pb = fmaf(xs[d], Wb[d], pb);
        pg = fmaf(xs[d], Wg[d], pg);
    }
    float v = acc + bv[t];
    g_v[b * NW + t] = v;

    red[t] = v * v; __syncthreads();
    for (int s = 32; s > 0; s >>= 1) { if (t < s) red[t] += red[t + s]; __syncthreads(); }
    if (t == 0) g_vn[b] = sqrtf(red[0]);
    __syncthreads();

    red[t] = pb; __syncthreads();
    for (int s = 32; s > 0; s >>= 1) { if (t < s) red[t] += red[t + s]; __syncthreads(); }
    if (t == 0) g_beta[b] = softplus_f(red[0] + bb[0]);
    __syncthreads();

    red[t] = pg; __syncthreads();
    for (int s = 32; s > 0; s >>= 1) { if (t < s) red[t] += red[t + s]; __syncthreads(); }
    if (t == 0) g_gamma[b] = 1.f + softplus_f(red[0] + bg[0]);
}

// ---------------- K0: memory row norms ----------------
__global__ void mn_kernel(const float* __restrict__ mem) {
    int r = blockIdx.x * blockDim.x + threadIdx.x;
    if (r >= NR) return;
    const float4* m4 = (const float4*)(mem + (size_t)r * NW);
    float s = 0.f;
    #pragma unroll
    for (int i = 0; i < NW / 4; ++i) {
        float4 t4 = m4[i];
        s += t4.x * t4.x + t4.y * t4.y + t4.z * t4.z + t4.w * t4.w;
    }
    g_mn[r] = sqrtf(s);
}

// ---------------- K2: sim logits = beta * (v . mem_r) / (vn*mn + eps) ----------------
__global__ void sim_gemm(const float* __restrict__ mem) {
    __shared__ float As[64][68];   // As[k][bi] = v[b0+bi][k]
    __shared__ float Bs[64][68];   // Bs[k][rj] = mem[r0+rj][k]
    int r0 = blockIdx.x * 64, b0 = blockIdx.y * 64;
    int tid = threadIdx.x;
    int tx = tid & 15, ty = tid >> 4;

    #pragma unroll
    for (int m = 0; m < 4; ++m) {
        int q = tid + m * 256;
        int row = q >> 4;
        int k4  = (q & 15) << 2;
        float4 a4 = *(const float4*)&g_v[(b0 + row) * NW + k4];
        As[k4 + 0][row] = a4.x; As[k4 + 1][row] = a4.y;
        As[k4 + 2][row] = a4.z; As[k4 + 3][row] = a4.w;
        float4 b4 = *(const float4*)&mem[(size_t)(r0 + row) * NW + k4];
        Bs[k4 + 0][row] = b4.x; Bs[k4 + 1][row] = b4.y;
        Bs[k4 + 2][row] = b4.z; Bs[k4 + 3][row] = b4.w;
    }
    __syncthreads();

    float acc[4][4] = {};
    #pragma unroll
    for (int k = 0; k < 64; ++k) {
        float4 ra = *(float4*)&As[k][ty * 4];
        float4 rb = *(float4*)&Bs[k][tx * 4];
        float a_[4] = {ra.x, ra.y, ra.z, ra.w};
        float b_[4] = {rb.x, rb.y, rb.z, rb.w};
        #pragma unroll
        for (int i = 0; i < 4; ++i)
            #pragma unroll
            for (int j = 0; j < 4; ++j)
                acc[i][j] = fmaf(a_[i], b_[j], acc[i][j]);
    }

    #pragma unroll
    for (int i = 0; i < 4; ++i) {
        int b = b0 + ty * 4 + i;
        float be = g_beta[b], vn = g_vn[b];
        #pragma unroll
        for (int j = 0; j < 4; ++j) {
            int r = r0 + tx * 4 + j;
            g_sim[(size_t)b * NR + r] = be * acc[i][j] / (vn * g_mn[r] + EPSF);
        }
    }
}

// ---------------- K3: softmax -> conv(K=3) -> pow(gamma) -> renorm (1024 thr/row) --------
__global__ void wa_kernel(const float* __restrict__ conv_k, const float* __restrict__ conv_b) {
    extern __shared__ float ws[];      // NR exp values
    __shared__ float red[32];
    int b = blockIdx.x, t = threadIdx.x;
    float* row = g_sim + (size_t)b * NR;

    float loc[16];
    float mx = -1e30f;
    #pragma unroll
    for (int i = 0; i < 16; ++i) { loc[i] = row[t + i * 1024]; mx = fmaxf(mx, loc[i]); }
    mx = blk_max(mx, red);

    float sum = 0.f;
    #pragma unroll
    for (int i = 0; i < 16; ++i) {
        float e = __expf(loc[i] - mx);
        ws[t + i * 1024] = e;
        sum += e;
    }
    sum = blk_sum(sum, red);   // also makes ws[] visible block-wide
    float inv = 1.f / sum;

    float c0 = conv_k[0], c1 = conv_k[1], c2 = conv_k[2], cb = conv_b[0];
    float gam = g_gamma[b];
    float asum = 0.f;
    #pragma unroll
    for (int i = 0; i < 16; ++i) {
        int r = t + i * 1024;
        float wl = (r > 0)      ? ws[r - 1] : 0.f;
        float wr = (r < NR - 1) ? ws[r + 1] : 0.f;
        float wc = fmaf(wl, c0, fmaf(ws[r], c1, wr * c2)) * inv + cb;
        float a = __powf(wc, gam);
        loc[i] = a; asum += a;
    }
    asum = blk_sum(asum, red);
    float invd = 1.f / (asum + (float)NR * EPSF);

    #pragma unroll
    for (int i = 0; i < 16; ++i) row[t + i * 1024] = loc[i] * invd;
}

// ---------------- K4: erase/add + mem2 ----------------
__global__ void add_gemm(const float* __restrict__ mem) {
    __shared__ float As[16][68];
    __shared__ float Bs[16][68];
    int r0 = blockIdx.x * 64;
    int tid = threadIdx.x, tx = tid & 15, ty = tid >> 4;
    float acc[4][4] = {};
    float er[4] = {};

    for (int k0 = 0; k0 < NB; k0 += 16) {
        int kk = tid >> 4, c4 = (tid & 15) << 2;
        *(float4*)&As[kk][c4] = *(const float4*)&g_sim[(size_t)(k0 + kk) * NR + r0 + c4];
        *(float4*)&Bs[kk][c4] = *(const float4*)&g_v[(k0 + kk) * NW + c4];
        __syncthreads();
        #pragma unroll
        for (int k = 0; k < 16; ++k) {
            float4 ra = *(float4*)&As[k][ty * 4];
            float4 rb = *(float4*)&Bs[k][tx * 4];
            float a_[4] = {ra.x, ra.y, ra.z, ra.w};
            float b_[4] = {rb.x, rb.y, rb.z, rb.w};
            er[0] += a_[0]; er[1] += a_[1]; er[2] += a_[2]; er[3] += a_[3];
            #pragma unroll
            for (int i = 0; i < 4; ++i)
                #pragma unroll
                for (int j = 0; j < 4; ++j)
                    acc[i][j] = fmaf(a_[i], b_[j], acc[i][j]);
        }
        __syncthreads();
    }
    const float invB = 1.f / (float)NB;
    #pragma unroll
    for (int i = 0; i < 4; ++i) {
        int r = r0 + ty * 4 + i;
        float e = er[i] * invB;
        #pragma unroll
        for (int j = 0; j < 4; ++j) {
            int w = tx * 4 + j;
            g_mem2[r * NW + w] = mem[(size_t)r * NW + w] * (1.f - e) + acc[i][j] * invB;
        }
    }
}

// ---------------- K5: p logits = x @ Wp + bp (128x128x8 fp32 tile) ----------------
__global__ void pl_gemm(const float* __restrict__ x, const float* __restrict__ Wp,
                        const float* __restrict__ bp) {
    __shared__ float As[8][132];
    __shared__ float Bs[8][132];
    int r0 = blockIdx.x * 128, b0 = blockIdx.y * 128;
    int tid = threadIdx.x;
    int tx = tid & 15, ty = tid >> 4;
    float acc[8][8] = {};

    for (int k0 = 0; k0 < ND; k0 += 8) {
        {
            int row = tid >> 1;
            int kk  = (tid & 1) << 2;
            float4 a4 = *(const float4*)&x[(size_t)(b0 + row) * ND + k0 + kk];
            As[kk + 0][row] = a4.x; As[kk + 1][row] = a4.y;
            As[kk + 2][row] = a4.z; As[kk + 3][row] = a4.w;
        }
        {
            int kk  = tid >> 5;
            int col = (tid & 31) << 2;
            *(float4*)&Bs[kk][col] = *(const float4*)&Wp[(size_t)(k0 + kk) * NR + r0 + col];
        }
        __syncthreads();
        #pragma unroll
        for (int k = 0; k < 8; ++k) {
            float ra[8], rb[8];
            *(float4*)&ra[0] = *(float4*)&As[k][ty * 4];
            *(float4*)&ra[4] = *(float4*)&As[k][64 + ty * 4];
            *(float4*)&rb[0] = *(float4*)&Bs[k][tx * 4];
            *(float4*)&rb[4] = *(float4*)&Bs[k][64 + tx * 4];
            #pragma unroll
            for (int i = 0; i < 8; ++i)
                #pragma unroll
                for (int j = 0; j < 8; ++j)
                    acc[i][j] = fmaf(ra[i], rb[j], acc[i][j]);
        }
        __syncthreads();
    }

    #pragma unroll
    for (int i = 0; i < 8; ++i) {
        int b = b0 + (i < 4 ? ty * 4 + i : 64 + ty * 4 + (i - 4));
        #pragma unroll
        for (int j = 0; j < 8; ++j) {
            int r = r0 + (j < 4 ? tx * 4 + j : 64 + tx * 4 + (j - 4));
            g_pl[(size_t)b * NR + r] = acc[i][j] + bp[r];
        }
    }
}

// ---------------- K6: per-row softmax stats for p (max, 1/sum) ----------------
__global__ void pstats_kernel() {
    __shared__ float red[32];
    int b = blockIdx.x, t = threadIdx.x;   // 1024 threads
    const float* row = g_pl + (size_t)b * NR;

    float loc[16];
    float mx = -1e30f;
    #pragma unroll
    for (int i = 0; i < 16; ++i) { loc[i] = row[t + i * 1024]; mx = fmaxf(mx, loc[i]); }
    mx = blk_max(mx, red);

    float sum = 0.f;
    #pragma unroll
    for (int i = 0; i < 16; ++i) sum += __expf(loc[i] - mx);
    sum = blk_sum(sum, red);

    if (t == 0) { g_pmx[b] = mx; g_pinv[b] = 1.f / sum; }
}

// ---------------- K7a: out = softmax(pl) @ mem2, exp fused, split-K=16 ----------------
__global__ void out_gemm() {
    __shared__ float As[16][68];   // As[kk][bi] = p[b0+bi][k0+kk]
    __shared__ float Bs[16][68];   // Bs[kk][w]  = mem2[k0+kk][w]
    int split = blockIdx.x;
    int b0 = blockIdx.y * 64;
    int kbase = split * (NR / NSPLIT);
    int tid = threadIdx.x, tx = tid & 15, ty = tid >> 4;
    float acc[4][4] = {};

    int li = tid >> 2;                      // row this thread loads for A
    float mxi  = g_pmx[b0 + li];
    float invi = g_pinv[b0 + li];

    for (int k0 = kbase; k0 < kbase + NR / NSPLIT; k0 += 16) {
        {
            int kq = (tid & 3) << 2;
            float4 a4 = *(const float4*)&g_pl[(size_t)(b0 + li) * NR + k0 + kq];
            As[kq + 0][li] = __expf(a4.x - mxi) * invi;
            As[kq + 1][li] = __expf(a4.y - mxi) * invi;
            As[kq + 2][li] = __expf(a4.z - mxi) * invi;
            As[kq + 3][li] = __expf(a4.w - mxi) * invi;
        }
        {
            int kk = tid >> 4, c4 = (tid & 15) << 2;
            *(float4*)&Bs[kk][c4] = *(const float4*)&g_mem2[(k0 + kk) * NW + c4];
        }
        __syncthreads();
        #pragma unroll
        for (int k = 0; k < 16; ++k) {
            float4 ra = *(float4*)&As[k][ty * 4];
            float4 rb = *(float4*)&Bs[k][tx * 4];
            float a_[4] = {ra.x, ra.y, ra.z, ra.w};
            float b_[4] = {rb.x, rb.y, rb.z, rb.w};
            #pragma unroll
            for (int i = 0; i < 4; ++i)
                #pragma unroll
                for (int j = 0; j < 4; ++j)
                    acc[i][j] = fmaf(a_[i], b_[j], acc[i][j]);
        }
        __syncthreads();
    }
    #pragma unroll
    for (int i = 0; i < 4; ++i)
        #pragma unroll
        for (int j = 0; j < 4; ++j)
            g_part[(size_t)split * (NB * NW) + (b0 + ty * 4 + i) * NW + tx * 4 + j] = acc[i][j];
}

__global__ void out_reduce(float* __restrict__ out) {
    int i = blockIdx.x * blockDim.x + threadIdx.x;
    float s = 0.f;
    #pragma unroll
    for (int p = 0; p < NSPLIT; ++p) s += g_part[(size_t)p * (NB * NW) + i];
    out[i] = s;
}

// ---------------- launch ----------------
extern "C" void kernel_launch(void* const* d_in, const int* in_sizes, int n_in,
                              void* d_out, int out_size) {
    const float* x   = (const float*)d_in[0];
    const float* Wv  = (const float*)d_in[1];
    const float* bv  = (const float*)d_in[2];
    const float* Wb  = (const float*)d_in[3];
    const float* bb  = (const float*)d_in[4];
    const float* Wg  = (const float*)d_in[5];
    const float* bg  = (const float*)d_in[6];
    const float* Wp  = (const float*)d_in[7];
    const float* bp  = (const float*)d_in[8];
    const float* ck  = (const float*)d_in[9];
    const float* cbv = (const float*)d_in[10];
    const float* mem = (const float*)d_in[11];
    float* out = (float*)d_out;
    (void)in_sizes; (void)n_in; (void)out_size;

    cudaFuncSetAttribute(wa_kernel, cudaFuncAttributeMaxDynamicSharedMemorySize, NR * 4);

    heads_kernel<<<NB, 64>>>(x, Wv, bv, Wb, bb, Wg, bg);
    mn_kernel<<<NR / 256, 256>>>(mem);
    sim_gemm<<<dim3(NR / 64, NB / 64), 256>>>(mem);
    wa_kernel<<<NB, 1024, NR * 4>>>(ck, cbv);
    add_gemm<<<NR / 64, 256>>>(mem);
    pl_gemm<<<dim3(NR / 128, NB / 128), 256>>>(x, Wp, bp);
    pstats_kernel<<<NB, 1024>>>();
    out_gemm<<<dim3(NSPLIT, NB / 64), 256>>>();
    out_reduce<<<NB * NW / 256, 256>>>(out);
}

// round 4
// speedup vs baseline: 1.5555x; 1.2209x over previous
#include <cuda_runtime.h>
#include <cuda_bf16.h>
#include <math.h>
#include <cstdint>

#define NB 1024
#define ND 256
#define NR 16384
#define NW 64
#define NSPLIT 16
#define EPSF 1e-16f
#define KCAT 768

// ---------------- scratch (no allocations allowed) ----------------
__device__ float g_sim[(size_t)NB * NR];   // beta*sim logits, then a (in place)
__device__ float g_pl [(size_t)NB * NR];   // p logits (raw; exp fused into out_gemm)
__device__ float g_v  [NB * NW];
__device__ float g_vn [NB];
__device__ float g_beta[NB];
__device__ float g_gamma[NB];
__device__ float g_mn [NR];
__device__ float g_mem2[NR * NW];
__device__ float g_part[NSPLIT * NB * NW];
__device__ float g_pmx [NB];
__device__ float g_pinv[NB];
__device__ __nv_bfloat16 g_xcat[(size_t)NB * KCAT];   // [x_hi | x_lo | x_hi]
__device__ __nv_bfloat16 g_wcat[(size_t)NR * KCAT];   // [W_hi | W_hi | W_lo] (transposed)

__device__ __forceinline__ float softplus_f(float z) {
    return z > 0.f ? z + log1pf(expf(-z)) : log1pf(expf(z));
}

__device__ __forceinline__ uint32_t smem_u32(const void* p) {
    uint32_t a;
    asm("{ .reg .u64 t; cvta.to.shared.u64 t, %1; cvt.u32.u64 %0, t; }" : "=r"(a) : "l"(p));
    return a;
}
__device__ __forceinline__ void ldsm_x4(uint32_t& r0, uint32_t& r1, uint32_t& r2, uint32_t& r3,
                                        uint32_t addr) {
    asm volatile("ldmatrix.sync.aligned.m8n8.x4.shared.b16 {%0, %1, %2, %3}, [%4];"
                 : "=r"(r0), "=r"(r1), "=r"(r2), "=r"(r3) : "r"(addr));
}
__device__ __forceinline__ void mma16816(float* d, const uint32_t* a, const uint32_t* b) {
    asm volatile(
        "mma.sync.aligned.m16n8k16.row.col.f32.bf16.bf16.f32 "
        "{%0, %1, %2, %3}, {%4, %5, %6, %7}, {%8, %9}, {%0, %1, %2, %3};"
        : "+f"(d[0]), "+f"(d[1]), "+f"(d[2]), "+f"(d[3])
        : "r"(a[0]), "r"(a[1]), "r"(a[2]), "r"(a[3]), "r"(b[0]), "r"(b[1]));
}

// block reductions for 1024 threads (32 warps)
__device__ __forceinline__ float blk_max(float v, float* red) {
    int lane = threadIdx.x & 31, w = threadIdx.x >> 5;
    #pragma unroll
    for (int o = 16; o; o >>= 1) v = fmaxf(v, __shfl_xor_sync(0xffffffffu, v, o));
    if (!lane) red[w] = v;
    __syncthreads();
    if (w == 0) {
        v = red[lane];
        #pragma unroll
        for (int o = 16; o; o >>= 1) v = fmaxf(v, __shfl_xor_sync(0xffffffffu, v, o));
        if (!lane) red[0] = v;
    }
    __syncthreads();
    v = red[0];
    __syncthreads();
    return v;
}
__device__ __forceinline__ float blk_sum(float v, float* red) {
    int lane = threadIdx.x & 31, w = threadIdx.x >> 5;
    #pragma unroll
    for (int o = 16; o; o >>= 1) v += __shfl_xor_sync(0xffffffffu, v, o);
    if (!lane) red[w] = v;
    __syncthreads();
    if (w == 0) {
        v = red[lane];
        #pragma unroll
        for (int o = 16; o; o >>= 1) v += __shfl_xor_sync(0xffffffffu, v, o);
        if (!lane) red[0] = v;
    }
    __syncthreads();
    v = red[0];
    __syncthreads();
    return v;
}

// ---------------- K1: controller heads: v, |v|, beta, gamma ----------------
__global__ void heads_kernel(const float* __restrict__ x,
                             const float* __restrict__ Wv, const float* __restrict__ bv,
                             const float* __restrict__ Wb, const float* __restrict__ bb,
                             const float* __restrict__ Wg, const float* __restrict__ bg) {
    int b = blockIdx.x, t = threadIdx.x;        // 64 threads
    __shared__ float xs[ND];
    __shared__ float red[64];
    for (int i = t; i < ND; i += 64) xs[i] = x[b * ND + i];
    __syncthreads();

    float acc = 0.f;
    #pragma unroll 8
    for (int d = 0; d < ND; ++d) acc = fmaf(xs[d], Wv[d * NW + t], acc);
    float pb = 0.f, pg = 0.f;
    for (int d = t; d < ND; d += 64) {
        pb = fmaf(xs[d], Wb[d], pb);
        pg = fmaf(xs[d], Wg[d], pg);
    }
    float v = acc + bv[t];
    g_v[b * NW + t] = v;

    red[t] = v * v; __syncthreads();
    for (int s = 32; s > 0; s >>= 1) { if (t < s) red[t] += red[t + s]; __syncthreads(); }
    if (t == 0) g_vn[b] = sqrtf(red[0]);
    __syncthreads();

    red[t] = pb; __syncthreads();
    for (int s = 32; s > 0; s >>= 1) { if (t < s) red[t] += red[t + s]; __syncthreads(); }
    if (t == 0) g_beta[b] = softplus_f(red[0] + bb[0]);
    __syncthreads();

    red[t] = pg; __syncthreads();
    for (int s = 32; s > 0; s >>= 1) { if (t < s) red[t] += red[t + s]; __syncthreads(); }
    if (t == 0) g_gamma[b] = 1.f + softplus_f(red[0] + bg[0]);
}

// ---------------- K0: memory row norms ----------------
__global__ void mn_kernel(const float* __restrict__ mem) {
    int r = blockIdx.x * blockDim.x + threadIdx.x;
    if (r >= NR) return;
    const float4* m4 = (const float4*)(mem + (size_t)r * NW);
    float s = 0.f;
    #pragma unroll
    for (int i = 0; i < NW / 4; ++i) {
        float4 t4 = m4[i];
        s += t4.x * t4.x + t4.y * t4.y + t4.z * t4.z + t4.w * t4.w;
    }
    g_mn[r] = sqrtf(s);
}

// ---------------- K2: sim logits = beta * (v . mem_r) / (vn*mn + eps) ----------------
__global__ void sim_gemm(const float* __restrict__ mem) {
    __shared__ float As[64][68];
    __shared__ float Bs[64][68];
    int r0 = blockIdx.x * 64, b0 = blockIdx.y * 64;
    int tid = threadIdx.x;
    int tx = tid & 15, ty = tid >> 4;

    #pragma unroll
    for (int m = 0; m < 4; ++m) {
        int q = tid + m * 256;
        int row = q >> 4;
        int k4  = (q & 15) << 2;
        float4 a4 = *(const float4*)&g_v[(b0 + row) * NW + k4];
        As[k4 + 0][row] = a4.x; As[k4 + 1][row] = a4.y;
        As[k4 + 2][row] = a4.z; As[k4 + 3][row] = a4.w;
        float4 b4 = *(const float4*)&mem[(size_t)(r0 + row) * NW + k4];
        Bs[k4 + 0][row] = b4.x; Bs[k4 + 1][row] = b4.y;
        Bs[k4 + 2][row] = b4.z; Bs[k4 + 3][row] = b4.w;
    }
    __syncthreads();

    float acc[4][4] = {};
    #pragma unroll
    for (int k = 0; k < 64; ++k) {
        float4 ra = *(float4*)&As[k][ty * 4];
        float4 rb = *(float4*)&Bs[k][tx * 4];
        float a_[4] = {ra.x, ra.y, ra.z, ra.w};
        float b_[4] = {rb.x, rb.y, rb.z, rb.w};
        #pragma unroll
        for (int i = 0; i < 4; ++i)
            #pragma unroll
            for (int j = 0; j < 4; ++j)
                acc[i][j] = fmaf(a_[i], b_[j], acc[i][j]);
    }

    #pragma unroll
    for (int i = 0; i < 4; ++i) {
        int b = b0 + ty * 4 + i;
        float be = g_beta[b], vn = g_vn[b];
        #pragma unroll
        for (int j = 0; j < 4; ++j) {
            int r = r0 + tx * 4 + j;
            g_sim[(size_t)b * NR + r] = be * acc[i][j] / (vn * g_mn[r] + EPSF);
        }
    }
}

// ---------------- K3: softmax -> conv(K=3) -> pow(gamma) -> renorm (1024 thr/row) --------
__global__ void wa_kernel(const float* __restrict__ conv_k, const float* __restrict__ conv_b) {
    extern __shared__ float ws[];      // NR exp values
    __shared__ float red[32];
    int b = blockIdx.x, t = threadIdx.x;
    float* row = g_sim + (size_t)b * NR;

    float loc[16];
    float mx = -1e30f;
    #pragma unroll
    for (int i = 0; i < 16; ++i) { loc[i] = row[t + i * 1024]; mx = fmaxf(mx, loc[i]); }
    mx = blk_max(mx, red);

    float sum = 0.f;
    #pragma unroll
    for (int i = 0; i < 16; ++i) {
        float e = __expf(loc[i] - mx);
        ws[t + i * 1024] = e;
        sum += e;
    }
    sum = blk_sum(sum, red);
    float inv = 1.f / sum;

    float c0 = conv_k[0], c1 = conv_k[1], c2 = conv_k[2], cb = conv_b[0];
    float gam = g_gamma[b];
    float asum = 0.f;
    #pragma unroll
    for (int i = 0; i < 16; ++i) {
        int r = t + i * 1024;
        float wl = (r > 0)      ? ws[r - 1] : 0.f;
        float wr = (r < NR - 1) ? ws[r + 1] : 0.f;
        float wc = fmaf(wl, c0, fmaf(ws[r], c1, wr * c2)) * inv + cb;
        float a = __powf(wc, gam);
        loc[i] = a; asum += a;
    }
    asum = blk_sum(asum, red);
    float invd = 1.f / (asum + (float)NR * EPSF);

    #pragma unroll
    for (int i = 0; i < 16; ++i) row[t + i * 1024] = loc[i] * invd;
}

// ---------------- K4: erase/add + mem2 ----------------
__global__ void add_gemm(const float* __restrict__ mem) {
    __shared__ float As[16][68];
    __shared__ float Bs[16][68];
    int r0 = blockIdx.x * 64;
    int tid = threadIdx.x, tx = tid & 15, ty = tid >> 4;
    float acc[4][4] = {};
    float er[4] = {};

    for (int k0 = 0; k0 < NB; k0 += 16) {
        int kk = tid >> 4, c4 = (tid & 15) << 2;
        *(float4*)&As[kk][c4] = *(const float4*)&g_sim[(size_t)(k0 + kk) * NR + r0 + c4];
        *(float4*)&Bs[kk][c4] = *(const float4*)&g_v[(k0 + kk) * NW + c4];
        __syncthreads();
        #pragma unroll
        for (int k = 0; k < 16; ++k) {
            float4 ra = *(float4*)&As[k][ty * 4];
            float4 rb = *(float4*)&Bs[k][tx * 4];
            float a_[4] = {ra.x, ra.y, ra.z, ra.w};
            float b_[4] = {rb.x, rb.y, rb.z, rb.w};
            er[0] += a_[0]; er[1] += a_[1]; er[2] += a_[2]; er[3] += a_[3];
            #pragma unroll
            for (int i = 0; i < 4; ++i)
                #pragma unroll
                for (int j = 0; j < 4; ++j)
                    acc[i][j] = fmaf(a_[i], b_[j], acc[i][j]);
        }
        __syncthreads();
    }
    const float invB = 1.f / (float)NB;
    #pragma unroll
    for (int i = 0; i < 4; ++i) {
        int r = r0 + ty * 4 + i;
        float e = er[i] * invB;
        #pragma unroll
        for (int j = 0; j < 4; ++j) {
            int w = tx * 4 + j;
            g_mem2[r * NW + w] = mem[(size_t)r * NW + w] * (1.f - e) + acc[i][j] * invB;
        }
    }
}

// ---------------- prep: xcat = [x_hi | x_lo | x_hi] (bf16, K=768) ----------------
__global__ void xcat_kernel(const float* __restrict__ x) {
    int i = blockIdx.x * 256 + threadIdx.x;   // < NB*ND
    int b = i >> 8, k = i & 255;
    float f = x[i];
    __nv_bfloat16 h = __float2bfloat16(f);
    __nv_bfloat16 l = __float2bfloat16(f - __bfloat162float(h));
    g_xcat[(size_t)b * KCAT + k]       = h;
    g_xcat[(size_t)b * KCAT + 256 + k] = l;
    g_xcat[(size_t)b * KCAT + 512 + k] = h;
}

// ---------------- prep: wcat[n][k] = [Wp_hi | Wp_hi | Wp_lo] transposed ----------------
__global__ void wcat_kernel(const float* __restrict__ Wp) {
    __shared__ float t[32][33];
    int n0 = blockIdx.x * 32, k0 = blockIdx.y * 32;
    int tx = threadIdx.x, ty = threadIdx.y;   // (32, 8)
    #pragma unroll
    for (int i = 0; i < 4; ++i)
        t[ty + 8 * i][tx] = Wp[(size_t)(k0 + ty + 8 * i) * NR + n0 + tx];   // t[k][n]
    __syncthreads();
    #pragma unroll
    for (int i = 0; i < 4; ++i) {
        int row = ty + 8 * i;                 // local n
        float f = t[tx][row];                 // Wp[k0+tx][n0+row]
        __nv_bfloat16 h = __float2bfloat16(f);
        __nv_bfloat16 l = __float2bfloat16(f - __bfloat162float(h));
        size_t base = (size_t)(n0 + row) * KCAT + k0 + tx;
        g_wcat[base]       = h;
        g_wcat[base + 256] = h;
        g_wcat[base + 512] = l;
    }
}

// ---------------- K5: p logits via mma.sync bf16 split GEMM ----------------
// CTA tile 128(M) x 128(N), BK=32, 8 warps each 64x32. NT layout, k-contiguous.
#define PLS 40   // padded row stride in bf16 elements (80B: conflict-free ldmatrix)

__global__ void __launch_bounds__(256, 2)
pl_mma_kernel(const float* __restrict__ bp) {
    __shared__ __nv_bfloat16 As[128][PLS];
    __shared__ __nv_bfloat16 Bs[128][PLS];
    int tid = threadIdx.x;
    int lane = tid & 31, wid = tid >> 5;
    int n0 = blockIdx.x * 128;
    int b0 = blockIdx.y * 128;
    int wm0 = (wid & 1) * 64;       // warp M offset
    int wn0 = (wid >> 1) * 32;      // warp N offset

    float d[4][4][4] = {};          // [mi][ni][reg]

    uint32_t as_base = smem_u32(&As[0][0]);
    uint32_t bs_base = smem_u32(&Bs[0][0]);
    // ldmatrix source addresses (fixed per thread, k0 added per step)
    int a_row = wm0 + (lane & 15);
    int a_kof = (lane >> 4) * 8;
    int b_rof = ((lane >> 4) * 8) + (lane & 7);   // n row offset within 16-row group
    int b_kof = ((lane >> 3) & 1) * 8;

    for (int kc = 0; kc < KCAT / 32; ++kc) {
        // load A,B tiles: 128 rows x 32 bf16 (64B) each
        #pragma unroll
        for (int i = 0; i < 2; ++i) {
            int q = tid + i * 256;             // 0..511
            int row = q >> 2, seg = (q & 3) * 8;
            *(uint4*)&As[row][seg] = *(const uint4*)&g_xcat[(size_t)(b0 + row) * KCAT + kc * 32 + seg];
            *(uint4*)&Bs[row][seg] = *(const uint4*)&g_wcat[(size_t)(n0 + row) * KCAT + kc * 32 + seg];
        }
        __syncthreads();

        #pragma unroll
        for (int ks = 0; ks < 2; ++ks) {
            int k0 = ks * 16;
            uint32_t a[4][4];
            #pragma unroll
            for (int mi = 0; mi < 4; ++mi) {
                uint32_t addr = as_base + ((a_row + mi * 16) * PLS + k0 + a_kof) * 2;
                ldsm_x4(a[mi][0], a[mi][1], a[mi][2], a[mi][3], addr);
            }
            uint32_t bfr[2][4];
            #pragma unroll
            for (int nj = 0; nj < 2; ++nj) {
                uint32_t addr = bs_base + ((wn0 + nj * 16 + b_rof) * PLS + k0 + b_kof) * 2;
                ldsm_x4(bfr[nj][0], bfr[nj][1], bfr[nj][2], bfr[nj][3], addr);
            }
            #pragma unroll
            for (int mi = 0; mi < 4; ++mi)
                #pragma unroll
                for (int ni = 0; ni < 4; ++ni)
                    mma16816(d[mi][ni], a[mi], &bfr[ni >> 1][(ni & 1) * 2]);
        }
        __syncthreads();
    }

    // epilogue: add bias, store float2 per fragment half
    int gr = lane >> 2, gc = (lane & 3) * 2;
    #pragma unroll
    for (int mi = 0; mi < 4; ++mi) {
        int r1 = b0 + wm0 + mi * 16 + gr;
        #pragma unroll
        for (int ni = 0; ni < 4; ++ni) {
            int c = n0 + wn0 + ni * 8 + gc;
            float bpx = bp[c], bpy = bp[c + 1];
            *(float2*)&g_pl[(size_t)r1 * NR + c] =
                make_float2(d[mi][ni][0] + bpx, d[mi][ni][1] + bpy);
            *(float2*)&g_pl[(size_t)(r1 + 8) * NR + c] =
                make_float2(d[mi][ni][2] + bpx, d[mi][ni][3] + bpy);
        }
    }
}

// ---------------- K6: per-row softmax stats for p (max, 1/sum) ----------------
__global__ void pstats_kernel() {
    __shared__ float red[32];
    int b = blockIdx.x, t = threadIdx.x;   // 1024 threads
    const float* row = g_pl + (size_t)b * NR;

    float loc[16];
    float mx = -1e30f;
    #pragma unroll
    for (int i = 0; i < 16; ++i) { loc[i] = row[t + i * 1024]; mx = fmaxf(mx, loc[i]); }
    mx = blk_max(mx, red);

    float sum = 0.f;
    #pragma unroll
    for (int i = 0; i < 16; ++i) sum += __expf(loc[i] - mx);
    sum = blk_sum(sum, red);

    if (t == 0) { g_pmx[b] = mx; g_pinv[b] = 1.f / sum; }
}

// ---------------- K7a: out = softmax(pl) @ mem2, exp fused, split-K=16 ----------------
__global__ void out_gemm() {
    __shared__ float As[16][68];
    __shared__ float Bs[16][68];
    int split = blockIdx.x;
    int b0 = blockIdx.y * 64;
    int kbase = split * (NR / NSPLIT);
    int tid = threadIdx.x, tx = tid & 15, ty = tid >> 4;
    float acc[4][4] = {};

    int li = tid >> 2;
    float mxi  = g_pmx[b0 + li];
    float invi = g_pinv[b0 + li];

    for (int k0 = kbase; k0 < kbase + NR / NSPLIT; k0 += 16) {
        {
            int kq = (tid & 3) << 2;
            float4 a4 = *(const float4*)&g_pl[(size_t)(b0 + li) * NR + k0 + kq];
            As[kq + 0][li] = __expf(a4.x - mxi) * invi;
            As[kq + 1][li] = __expf(a4.y - mxi) * invi;
            As[kq + 2][li] = __expf(a4.z - mxi) * invi;
            As[kq + 3][li] = __expf(a4.w - mxi) * invi;
        }
        {
            int kk = tid >> 4, c4 = (tid & 15) << 2;
            *(float4*)&Bs[kk][c4] = *(const float4*)&g_mem2[(k0 + kk) * NW + c4];
        }
        __syncthreads();
        #pragma unroll
        for (int k = 0; k < 16; ++k) {
            float4 ra = *(float4*)&As[k][ty * 4];
            float4 rb = *(float4*)&Bs[k][tx * 4];
            float a_[4] = {ra.x, ra.y, ra.z, ra.w};
            float b_[4] = {rb.x, rb.y, rb.z, rb.w};
            #pragma unroll
            for (int i = 0; i < 4; ++i)
                #pragma unroll
                for (int j = 0; j < 4; ++j)
                    acc[i][j] = fmaf(a_[i], b_[j], acc[i][j]);
        }
        __syncthreads();
    }
    #pragma unroll
    for (int i = 0; i < 4; ++i)
        #pragma unroll
        for (int j = 0; j < 4; ++j)
            g_part[(size_t)split * (NB * NW) + (b0 + ty * 4 + i) * NW + tx * 4 + j] = acc[i][j];
}

__global__ void out_reduce(float* __restrict__ out) {
    int i = blockIdx.x * blockDim.x + threadIdx.x;
    float s = 0.f;
    #pragma unroll
    for (int p = 0; p < NSPLIT; ++p) s += g_part[(size_t)p * (NB * NW) + i];
    out[i] = s;
}

// ---------------- launch ----------------
extern "C" void kernel_launch(void* const* d_in, const int* in_sizes, int n_in,
                              void* d_out, int out_size) {
    const float* x   = (const float*)d_in[0];
    const float* Wv  = (const float*)d_in[1];
    const float* bv  = (const float*)d_in[2];
    const float* Wb  = (const float*)d_in[3];
    const float* bb  = (const float*)d_in[4];
    const float* Wg  = (const float*)d_in[5];
    const float* bg  = (const float*)d_in[6];
    const float* Wp  = (const float*)d_in[7];
    const float* bp  = (const float*)d_in[8];
    const float* ck  = (const float*)d_in[9];
    const float* cbv = (const float*)d_in[10];
    const float* mem = (const float*)d_in[11];
    float* out = (float*)d_out;
    (void)in_sizes; (void)n_in; (void)out_size;

    cudaFuncSetAttribute(wa_kernel, cudaFuncAttributeMaxDynamicSharedMemorySize, NR * 4);

    heads_kernel<<<NB, 64>>>(x, Wv, bv, Wb, bb, Wg, bg);
    mn_kernel<<<NR / 256, 256>>>(mem);
    xcat_kernel<<<NB * ND / 256, 256>>>(x);
    wcat_kernel<<<dim3(NR / 32, ND / 32), dim3(32, 8)>>>(Wp);
    sim_gemm<<<dim3(NR / 64, NB / 64), 256>>>(mem);
    wa_kernel<<<NB, 1024, NR * 4>>>(ck, cbv);
    add_gemm<<<NR / 64, 256>>>(mem);
    pl_mma_kernel<<<dim3(NR / 128, NB / 128), 256>>>(bp);
    pstats_kernel<<<NB, 1024>>>();
    out_gemm<<<dim3(NSPLIT, NB / 64), 256>>>();
    out_reduce<<<NB * NW / 256, 256>>>(out);
}

// round 5
// speedup vs baseline: 1.9897x; 1.2791x over previous
#include <cuda_runtime.h>
#include <cuda_bf16.h>
#include <math.h>
#include <cstdint>

#define NB 1024
#define ND 256
#define NR 16384
#define NW 64
#define NSPLIT 64
#define ADDS 4
#define EPSF 1e-16f
#define KCAT 768

// ---------------- scratch (no allocations allowed) ----------------
__device__ float g_sim[(size_t)NB * NR];   // beta*sim logits, then a (in place)
__device__ float g_pl [(size_t)NB * NR];   // p logits (raw; exp fused into out_gemm)
__device__ float g_v  [NB * NW];
__device__ float g_vn [NB];
__device__ float g_beta[NB];
__device__ float g_gamma[NB];
__device__ float g_mn [NR];
__device__ float g_mem2[NR * NW];
__device__ float g_part[(size_t)NSPLIT * NB * NW];
__device__ float g_addp[(size_t)ADDS * NR * NW];
__device__ float g_erp [(size_t)ADDS * NR];
__device__ float g_pmx [NB];
__device__ float g_pinv[NB];
__device__ __nv_bfloat16 g_xcat[(size_t)NB * KCAT];   // [x_hi | x_lo | x_hi]
__device__ __nv_bfloat16 g_wcat[(size_t)NR * KCAT];   // [W_hi | W_hi | W_lo] (transposed)
__device__ __nv_bfloat16 g_vh  [NB * NW];
__device__ __nv_bfloat16 g_memh[NR * NW];

__device__ __forceinline__ float softplus_f(float z) {
    return z > 0.f ? z + log1pf(expf(-z)) : log1pf(expf(z));
}

__device__ __forceinline__ uint32_t smem_u32(const void* p) {
    uint32_t a;
    asm("{ .reg .u64 t; cvta.to.shared.u64 t, %1; cvt.u32.u64 %0, t; }" : "=r"(a) : "l"(p));
    return a;
}
__device__ __forceinline__ void ldsm_x4(uint32_t& r0, uint32_t& r1, uint32_t& r2, uint32_t& r3,
                                        uint32_t addr) {
    asm volatile("ldmatrix.sync.aligned.m8n8.x4.shared.b16 {%0, %1, %2, %3}, [%4];"
                 : "=r"(r0), "=r"(r1), "=r"(r2), "=r"(r3) : "r"(addr));
}
__device__ __forceinline__ void mma16816(float* d, const uint32_t* a, const uint32_t* b) {
    asm volatile(
        "mma.sync.aligned.m16n8k16.row.col.f32.bf16.bf16.f32 "
        "{%0, %1, %2, %3}, {%4, %5, %6, %7}, {%8, %9}, {%0, %1, %2, %3};"
        : "+f"(d[0]), "+f"(d[1]), "+f"(d[2]), "+f"(d[3])
        : "r"(a[0]), "r"(a[1]), "r"(a[2]), "r"(a[3]), "r"(b[0]), "r"(b[1]));
}

// block reductions for 1024 threads (32 warps)
__device__ __forceinline__ float blk_max(float v, float* red) {
    int lane = threadIdx.x & 31, w = threadIdx.x >> 5;
    #pragma unroll
    for (int o = 16; o; o >>= 1) v = fmaxf(v, __shfl_xor_sync(0xffffffffu, v, o));
    if (!lane) red[w] = v;
    __syncthreads();
    if (w == 0) {
        v = red[lane];
        #pragma unroll
        for (int o = 16; o; o >>= 1) v = fmaxf(v, __shfl_xor_sync(0xffffffffu, v, o));
        if (!lane) red[0] = v;
    }
    __syncthreads();
    v = red[0];
    __syncthreads();
    return v;
}
__device__ __forceinline__ float blk_sum(float v, float* red) {
    int lane = threadIdx.x & 31, w = threadIdx.x >> 5;
    #pragma unroll
    for (int o = 16; o; o >>= 1) v += __shfl_xor_sync(0xffffffffu, v, o);
    if (!lane) red[w] = v;
    __syncthreads();
    if (w == 0) {
        v = red[lane];
        #pragma unroll
        for (int o = 16; o; o >>= 1) v += __shfl_xor_sync(0xffffffffu, v, o);
        if (!lane) red[0] = v;
    }
    __syncthreads();
    v = red[0];
    __syncthreads();
    return v;
}

// ---------------- K1: controller heads: v, |v|, beta, gamma ----------------
__global__ void heads_kernel(const float* __restrict__ x,
                             const float* __restrict__ Wv, const float* __restrict__ bv,
                             const float* __restrict__ Wb, const float* __restrict__ bb,
                             const float* __restrict__ Wg, const float* __restrict__ bg) {
    int b = blockIdx.x, t = threadIdx.x;        // 64 threads
    __shared__ float xs[ND];
    __shared__ float red[64];
    for (int i = t; i < ND; i += 64) xs[i] = x[b * ND + i];
    __syncthreads();

    float acc = 0.f;
    #pragma unroll 8
    for (int d = 0; d < ND; ++d) acc = fmaf(xs[d], Wv[d * NW + t], acc);
    float pb = 0.f, pg = 0.f;
    for (int d = t; d < ND; d += 64) {
        pb = fmaf(xs[d], Wb[d], pb);
        pg = fmaf(xs[d], Wg[d], pg);
    }
    float v = acc + bv[t];
    g_v[b * NW + t] = v;
    g_vh[b * NW + t] = __float2bfloat16(v);

    red[t] = v * v; __syncthreads();
    for (int s = 32; s > 0; s >>= 1) { if (t < s) red[t] += red[t + s]; __syncthreads(); }
    if (t == 0) g_vn[b] = sqrtf(red[0]);
    __syncthreads();

    red[t] = pb; __syncthreads();
    for (int s = 32; s > 0; s >>= 1) { if (t < s) red[t] += red[t + s]; __syncthreads(); }
    if (t == 0) g_beta[b] = softplus_f(red[0] + bb[0]);
    __syncthreads();

    red[t] = pg; __syncthreads();
    for (int s = 32; s > 0; s >>= 1) { if (t < s) red[t] += red[t + s]; __syncthreads(); }
    if (t == 0) g_gamma[b] = 1.f + softplus_f(red[0] + bg[0]);
}

// ---------------- K0: memory row norms ----------------
__global__ void mn_kernel(const float* __restrict__ mem) {
    int r = blockIdx.x * blockDim.x + threadIdx.x;
    if (r >= NR) return;
    const float4* m4 = (const float4*)(mem + (size_t)r * NW);
    float s = 0.f;
    #pragma unroll
    for (int i = 0; i < NW / 4; ++i) {
        float4 t4 = m4[i];
        s += t4.x * t4.x + t4.y * t4.y + t4.z * t4.z + t4.w * t4.w;
    }
    g_mn[r] = sqrtf(s);
}

// ---------------- prep: mem -> bf16 ----------------
__global__ void memh_kernel(const float* __restrict__ mem) {
    int i = blockIdx.x * 256 + threadIdx.x;    // NR*NW/4 float4 slots
    float4 f = *(const float4*)&mem[(size_t)i * 4];
    __nv_bfloat162 h0 = __float22bfloat162_rn(make_float2(f.x, f.y));
    __nv_bfloat162 h1 = __float22bfloat162_rn(make_float2(f.z, f.w));
    *(__nv_bfloat162*)&g_memh[(size_t)i * 4]     = h0;
    *(__nv_bfloat162*)&g_memh[(size_t)i * 4 + 2] = h1;
}

// ---------------- K2: sim via HMMA bf16 (plain bf16 is enough for the a-path) --------
// D[b][r] = v[b] . mem[r]; epilogue: beta/(vn*mn+eps). Tile 128x128, K=64.
#define SLS 72   // row stride (144 B, 16B-aligned, conflict-free: 36w*r mod 32 distinct)
__global__ void __launch_bounds__(256, 2)
sim_tc_kernel() {
    __shared__ __nv_bfloat16 As[128][SLS];
    __shared__ __nv_bfloat16 Bs[128][SLS];
    int tid = threadIdx.x;
    int lane = tid & 31, wid = tid >> 5;
    int n0 = blockIdx.x * 128;    // r
    int b0 = blockIdx.y * 128;    // b
    int wm0 = (wid & 1) * 64;
    int wn0 = (wid >> 1) * 32;

    // load A/B: 128 rows x 64 bf16 (8 uint4/row); 4 uint4 per thread each
    #pragma unroll
    for (int i = 0; i < 4; ++i) {
        int q = tid + i * 256;       // 0..1023
        int row = q >> 3, seg = (q & 7) * 8;
        *(uint4*)&As[row][seg] = *(const uint4*)&g_vh[(size_t)(b0 + row) * NW + seg];
        *(uint4*)&Bs[row][seg] = *(const uint4*)&g_memh[(size_t)(n0 + row) * NW + seg];
    }
    __syncthreads();

    float d[4][4][4] = {};
    uint32_t as_base = smem_u32(&As[0][0]);
    uint32_t bs_base = smem_u32(&Bs[0][0]);
    int a_row = wm0 + (lane & 15);
    int a_kof = (lane >> 4) * 8;
    int b_rof = ((lane >> 4) * 8) + (lane & 7);
    int b_kof = ((lane >> 3) & 1) * 8;

    #pragma unroll
    for (int ks = 0; ks < 4; ++ks) {
        int k0 = ks * 16;
        uint32_t a[4][4];
        #pragma unroll
        for (int mi = 0; mi < 4; ++mi) {
            uint32_t addr = as_base + ((a_row + mi * 16) * SLS + k0 + a_kof) * 2;
            ldsm_x4(a[mi][0], a[mi][1], a[mi][2], a[mi][3], addr);
        }
        uint32_t bfr[2][4];
        #pragma unroll
        for (int nj = 0; nj < 2; ++nj) {
            uint32_t addr = bs_base + ((wn0 + nj * 16 + b_rof) * SLS + k0 + b_kof) * 2;
            ldsm_x4(bfr[nj][0], bfr[nj][1], bfr[nj][2], bfr[nj][3], addr);
        }
        #pragma unroll
        for (int mi = 0; mi < 4; ++mi)
            #pragma unroll
            for (int ni = 0; ni < 4; ++ni)
                mma16816(d[mi][ni], a[mi], &bfr[ni >> 1][(ni & 1) * 2]);
    }

    int gr = lane >> 2, gc = (lane & 3) * 2;
    #pragma unroll
    for (int mi = 0; mi < 4; ++mi) {
        int bi0 = b0 + wm0 + mi * 16 + gr;
        float s0 = g_beta[bi0] , n0v = g_vn[bi0];
        float s1 = g_beta[bi0 + 8], n1v = g_vn[bi0 + 8];
        #pragma unroll
        for (int ni = 0; ni < 4; ++ni) {
            int c = n0 + wn0 + ni * 8 + gc;
            float m0 = g_mn[c], m1 = g_mn[c + 1];
            *(float2*)&g_sim[(size_t)bi0 * NR + c] = make_float2(
                s0 * d[mi][ni][0] / (n0v * m0 + EPSF),
                s0 * d[mi][ni][1] / (n0v * m1 + EPSF));
            *(float2*)&g_sim[(size_t)(bi0 + 8) * NR + c] = make_float2(
                s1 * d[mi][ni][2] / (n1v * m0 + EPSF),
                s1 * d[mi][ni][3] / (n1v * m1 + EPSF));
        }
    }
}

// ---------------- K3: softmax -> conv(K=3) -> pow(gamma) -> renorm (1024 thr/row) --------
__global__ void wa_kernel(const float* __restrict__ conv_k, const float* __restrict__ conv_b) {
    extern __shared__ float ws[];      // NR exp values
    __shared__ float red[32];
    int b = blockIdx.x, t = threadIdx.x;
    float* row = g_sim + (size_t)b * NR;

    float loc[16];
    float mx = -1e30f;
    #pragma unroll
    for (int i = 0; i < 16; ++i) { loc[i] = row[t + i * 1024]; mx = fmaxf(mx, loc[i]); }
    mx = blk_max(mx, red);

    float sum = 0.f;
    #pragma unroll
    for (int i = 0; i < 16; ++i) {
        float e = __expf(loc[i] - mx);
        ws[t + i * 1024] = e;
        sum += e;
    }
    sum = blk_sum(sum, red);
    float inv = 1.f / sum;

    float c0 = conv_k[0], c1 = conv_k[1], c2 = conv_k[2], cb = conv_b[0];
    float gam = g_gamma[b];
    float asum = 0.f;
    #pragma unroll
    for (int i = 0; i < 16; ++i) {
        int r = t + i * 1024;
        float wl = (r > 0)      ? ws[r - 1] : 0.f;
        float wr = (r < NR - 1) ? ws[r + 1] : 0.f;
        float wc = fmaf(wl, c0, fmaf(ws[r], c1, wr * c2)) * inv + cb;
        float a = __powf(wc, gam);
        loc[i] = a; asum += a;
    }
    asum = blk_sum(asum, red);
    float invd = 1.f / (asum + (float)NR * EPSF);

    #pragma unroll
    for (int i = 0; i < 16; ++i) row[t + i * 1024] = loc[i] * invd;
}

// ---------------- K4a: add/erase partials, split over B (ADDS splits) ----------------
__global__ void add_gemm_split() {
    __shared__ float As[16][68];
    __shared__ float Bs[16][68];
    int r0 = blockIdx.x * 64;
    int split = blockIdx.y;
    int tid = threadIdx.x, tx = tid & 15, ty = tid >> 4;
    float acc[4][4] = {};
    float er[4] = {};

    int kend = (split + 1) * (NB / ADDS);
    for (int k0 = split * (NB / ADDS); k0 < kend; k0 += 16) {
        int kk = tid >> 4, c4 = (tid & 15) << 2;
        *(float4*)&As[kk][c4] = *(const float4*)&g_sim[(size_t)(k0 + kk) * NR + r0 + c4];
        *(float4*)&Bs[kk][c4] = *(const float4*)&g_v[(k0 + kk) * NW + c4];
        __syncthreads();
        #pragma unroll
        for (int k = 0; k < 16; ++k) {
            float4 ra = *(float4*)&As[k][ty * 4];
            float4 rb = *(float4*)&Bs[k][tx * 4];
            float a_[4] = {ra.x, ra.y, ra.z, ra.w};
            float b_[4] = {rb.x, rb.y, rb.z, rb.w};
            er[0] += a_[0]; er[1] += a_[1]; er[2] += a_[2]; er[3] += a_[3];
            #pragma unroll
            for (int i = 0; i < 4; ++i)
                #pragma unroll
                for (int j = 0; j < 4; ++j)
                    acc[i][j] = fmaf(a_[i], b_[j], acc[i][j]);
        }
        __syncthreads();
    }
    #pragma unroll
    for (int i = 0; i < 4; ++i) {
        int r = r0 + ty * 4 + i;
        if (tx == 0) g_erp[(size_t)split * NR + r] = er[i];
        #pragma unroll
        for (int j = 0; j < 4; ++j)
            g_addp[((size_t)split * NR + r) * NW + tx * 4 + j] = acc[i][j];
    }
}

// ---------------- K4b: combine partials into mem2 ----------------
__global__ void mem2_combine(const float* __restrict__ mem) {
    int i = blockIdx.x * 256 + threadIdx.x;   // over NR*NW
    int r = i >> 6;
    float e = 0.f, ad = 0.f;
    #pragma unroll
    for (int s = 0; s < ADDS; ++s) {
        e  += g_erp[(size_t)s * NR + r];
        ad += g_addp[((size_t)s * NR + r) * NW + (i & 63)];
    }
    const float invB = 1.f / (float)NB;
    g_mem2[i] = mem[i] * (1.f - e * invB) + ad * invB;
}

// ---------------- prep: xcat = [x_hi | x_lo | x_hi] (bf16, K=768) ----------------
__global__ void xcat_kernel(const float* __restrict__ x) {
    int i = blockIdx.x * 256 + threadIdx.x;   // < NB*ND
    int b = i >> 8, k = i & 255;
    float f = x[i];
    __nv_bfloat16 h = __float2bfloat16(f);
    __nv_bfloat16 l = __float2bfloat16(f - __bfloat162float(h));
    g_xcat[(size_t)b * KCAT + k]       = h;
    g_xcat[(size_t)b * KCAT + 256 + k] = l;
    g_xcat[(size_t)b * KCAT + 512 + k] = h;
}

// ---------------- prep: wcat[n][k] = [Wp_hi | Wp_hi | Wp_lo] transposed ----------------
__global__ void wcat_kernel(const float* __restrict__ Wp) {
    __shared__ float t[32][33];
    int n0 = blockIdx.x * 32, k0 = blockIdx.y * 32;
    int tx = threadIdx.x, ty = threadIdx.y;   // (32, 8)
    #pragma unroll
    for (int i = 0; i < 4; ++i)
        t[ty + 8 * i][tx] = Wp[(size_t)(k0 + ty + 8 * i) * NR + n0 + tx];   // t[k][n]
    __syncthreads();
    #pragma unroll
    for (int i = 0; i < 4; ++i) {
        int row = ty + 8 * i;                 // local n
        float f = t[tx][row];                 // Wp[k0+tx][n0+row]
        __nv_bfloat16 h = __float2bfloat16(f);
        __nv_bfloat16 l = __float2bfloat16(f - __bfloat162float(h));
        size_t base = (size_t)(n0 + row) * KCAT + k0 + tx;
        g_wcat[base]       = h;
        g_wcat[base + 256] = h;
        g_wcat[base + 512] = l;
    }
}

// ---------------- K5: p logits via mma.sync, reg-prefetch + double-buffered smem -------
#define PLS 40   // padded row stride in bf16 (80B rows, 16B-aligned, conflict-free)
#define PLK (KCAT / 32)

__global__ void __launch_bounds__(256, 2)
pl_mma_kernel(const float* __restrict__ bp) {
    __shared__ __nv_bfloat16 As[2][128][PLS];
    __shared__ __nv_bfloat16 Bs[2][128][PLS];
    int tid = threadIdx.x;
    int lane = tid & 31, wid = tid >> 5;
    int n0 = blockIdx.x * 128;
    int b0 = blockIdx.y * 128;
    int wm0 = (wid & 1) * 64;
    int wn0 = (wid >> 1) * 32;

    float d[4][4][4] = {};

    uint32_t as_base = smem_u32(&As[0][0][0]);
    uint32_t bs_base = smem_u32(&Bs[0][0][0]);
    const uint32_t bufsz = 128 * PLS * 2;
    int a_row = wm0 + (lane & 15);
    int a_kof = (lane >> 4) * 8;
    int b_rof = ((lane >> 4) * 8) + (lane & 7);
    int b_kof = ((lane >> 3) & 1) * 8;

    // per-thread load slots: 2 uint4 for A, 2 for B
    int lrow[2], lseg[2];
    #pragma unroll
    for (int i = 0; i < 2; ++i) { int q = tid + i * 256; lrow[i] = q >> 2; lseg[i] = (q & 3) * 8; }

    uint4 pa[2], pb[2];
    #pragma unroll
    for (int i = 0; i < 2; ++i) {
        pa[i] = *(const uint4*)&g_xcat[(size_t)(b0 + lrow[i]) * KCAT + lseg[i]];
        pb[i] = *(const uint4*)&g_wcat[(size_t)(n0 + lrow[i]) * KCAT + lseg[i]];
    }
    #pragma unroll
    for (int i = 0; i < 2; ++i) {
        *(uint4*)&As[0][lrow[i]][lseg[i]] = pa[i];
        *(uint4*)&Bs[0][lrow[i]][lseg[i]] = pb[i];
    }
    __syncthreads();

    for (int kc = 0; kc < PLK; ++kc) {
        int cur = kc & 1;
        if (kc + 1 < PLK) {
            #pragma unroll
            for (int i = 0; i < 2; ++i) {
                pa[i] = *(const uint4*)&g_xcat[(size_t)(b0 + lrow[i]) * KCAT + (kc + 1) * 32 + lseg[i]];
                pb[i] = *(const uint4*)&g_wcat[(size_t)(n0 + lrow[i]) * KCAT + (kc + 1) * 32 + lseg[i]];
            }
        }
        uint32_t abase = as_base + cur * bufsz;
        uint32_t bbase = bs_base + cur * bufsz;
        #pragma unroll
        for (int ks = 0; ks < 2; ++ks) {
            int k0 = ks * 16;
            uint32_t a[4][4];
            #pragma unroll
            for (int mi = 0; mi < 4; ++mi) {
                uint32_t addr = abase + ((a_row + mi * 16) * PLS + k0 + a_kof) * 2;
                ldsm_x4(a[mi][0], a[mi][1], a[mi][2], a[mi][3], addr);
            }
            uint32_t bfr[2][4];
            #pragma unroll
            for (int nj = 0; nj < 2; ++nj) {
                uint32_t addr = bbase + ((wn0 + nj * 16 + b_rof) * PLS + k0 + b_kof) * 2;
                ldsm_x4(bfr[nj][0], bfr[nj][1], bfr[nj][2], bfr[nj][3], addr);
            }
            #pragma unroll
            for (int mi = 0; mi < 4; ++mi)
                #pragma unroll
                for (int ni = 0; ni < 4; ++ni)
                    mma16816(d[mi][ni], a[mi], &bfr[ni >> 1][(ni & 1) * 2]);
        }
        if (kc + 1 < PLK) {
            int nxt = cur ^ 1;
            #pragma unroll
            for (int i = 0; i < 2; ++i) {
                *(uint4*)&As[nxt][lrow[i]][lseg[i]] = pa[i];
                *(uint4*)&Bs[nxt][lrow[i]][lseg[i]] = pb[i];
            }
        }
        __syncthreads();
    }

    // epilogue: add bias, store float2 per fragment half
    int gr = lane >> 2, gc = (lane & 3) * 2;
    #pragma unroll
    for (int mi = 0; mi < 4; ++mi) {
        int r1 = b0 + wm0 + mi * 16 + gr;
        #pragma unroll
        for (int ni = 0; ni < 4; ++ni) {
            int c = n0 + wn0 + ni * 8 + gc;
            float bpx = bp[c], bpy = bp[c + 1];
            *(float2*)&g_pl[(size_t)r1 * NR + c] =
                make_float2(d[mi][ni][0] + bpx, d[mi][ni][1] + bpy);
            *(float2*)&g_pl[(size_t)(r1 + 8) * NR + c] =
                make_float2(d[mi][ni][2] + bpx, d[mi][ni][3] + bpy);
        }
    }
}

// ---------------- K6: per-row softmax stats for p (max, 1/sum) ----------------
__global__ void pstats_kernel() {
    __shared__ float red[32];
    int b = blockIdx.x, t = threadIdx.x;   // 1024 threads
    const float* row = g_pl + (size_t)b * NR;

    float loc[16];
    float mx = -1e30f;
    #pragma unroll
    for (int i = 0; i < 16; ++i) { loc[i] = row[t + i * 1024]; mx = fmaxf(mx, loc[i]); }
    mx = blk_max(mx, red);

    float sum = 0.f;
    #pragma unroll
    for (int i = 0; i < 16; ++i) sum += __expf(loc[i] - mx);
    sum = blk_sum(sum, red);

    if (t == 0) { g_pmx[b] = mx; g_pinv[b] = 1.f / sum; }
}

// ---------------- K7a: out = softmax(pl) @ mem2, exp fused, split-K=64 ----------------
__global__ void out_gemm() {
    __shared__ float As[16][68];
    __shared__ float Bs[16][68];
    int split = blockIdx.x;
    int b0 = blockIdx.y * 64;
    int kbase = split * (NR / NSPLIT);
    int tid = threadIdx.x, tx = tid & 15, ty = tid >> 4;
    float acc[4][4] = {};

    int li = tid >> 2;
    float mxi  = g_pmx[b0 + li];
    float invi = g_pinv[b0 + li];

    for (int k0 = kbase; k0 < kbase + NR / NSPLIT; k0 += 16) {
        {
            int kq = (tid & 3) << 2;
            float4 a4 = *(const float4*)&g_pl[(size_t)(b0 + li) * NR + k0 + kq];
            As[kq + 0][li] = __expf(a4.x - mxi) * invi;
            As[kq + 1][li] = __expf(a4.y - mxi) * invi;
            As[kq + 2][li] = __expf(a4.z - mxi) * invi;
            As[kq + 3][li] = __expf(a4.w - mxi) * invi;
        }
        {
            int kk = tid >> 4, c4 = (tid & 15) << 2;
            *(float4*)&Bs[kk][c4] = *(const float4*)&g_mem2[(k0 + kk) * NW + c4];
        }
        __syncthreads();
        #pragma unroll
        for (int k = 0; k < 16; ++k) {
            float4 ra = *(float4*)&As[k][ty * 4];
            float4 rb = *(float4*)&Bs[k][tx * 4];
            float a_[4] = {ra.x, ra.y, ra.z, ra.w};
            float b_[4] = {rb.x, rb.y, rb.z, rb.w};
            #pragma unroll
            for (int i = 0; i < 4; ++i)
                #pragma unroll
                for (int j = 0; j < 4; ++j)
                    acc[i][j] = fmaf(a_[i], b_[j], acc[i][j]);
        }
        __syncthreads();
    }
    #pragma unroll
    for (int i = 0; i < 4; ++i)
        #pragma unroll
        for (int j = 0; j < 4; ++j)
            g_part[(size_t)split * (NB * NW) + (b0 + ty * 4 + i) * NW + tx * 4 + j] = acc[i][j];
}

__global__ void out_reduce(float* __restrict__ out) {
    int i = blockIdx.x * blockDim.x + threadIdx.x;
    float s = 0.f;
    #pragma unroll
    for (int p = 0; p < NSPLIT; ++p) s += g_part[(size_t)p * (NB * NW) + i];
    out[i] = s;
}

// ---------------- launch ----------------
extern "C" void kernel_launch(void* const* d_in, const int* in_sizes, int n_in,
                              void* d_out, int out_size) {
    const float* x   = (const float*)d_in[0];
    const float* Wv  = (const float*)d_in[1];
    const float* bv  = (const float*)d_in[2];
    const float* Wb  = (const float*)d_in[3];
    const float* bb  = (const float*)d_in[4];
    const float* Wg  = (const float*)d_in[5];
    const float* bg  = (const float*)d_in[6];
    const float* Wp  = (const float*)d_in[7];
    const float* bp  = (const float*)d_in[8];
    const float* ck  = (const float*)d_in[9];
    const float* cbv = (const float*)d_in[10];
    const float* mem = (const float*)d_in[11];
    float* out = (float*)d_out;
    (void)in_sizes; (void)n_in; (void)out_size;

    cudaFuncSetAttribute(wa_kernel, cudaFuncAttributeMaxDynamicSharedMemorySize, NR * 4);

    heads_kernel<<<NB, 64>>>(x, Wv, bv, Wb, bb, Wg, bg);
    mn_kernel<<<NR / 256, 256>>>(mem);
    memh_kernel<<<NR * NW / 4 / 256, 256>>>(mem);
    xcat_kernel<<<NB * ND / 256, 256>>>(x);
    wcat_kernel<<<dim3(NR / 32, ND / 32), dim3(32, 8)>>>(Wp);
    sim_tc_kernel<<<dim3(NR / 128, NB / 128), 256>>>();
    wa_kernel<<<NB, 1024, NR * 4>>>(ck, cbv);
    add_gemm_split<<<dim3(NR / 64, ADDS), 256>>>();
    mem2_combine<<<NR * NW / 256, 256>>>(mem);
    pl_mma_kernel<<<dim3(NR / 128, NB / 128), 256>>>(bp);
    pstats_kernel<<<NB, 1024>>>();
    out_gemm<<<dim3(NSPLIT, NB / 64), 256>>>();
    out_reduce<<<NB * NW / 256, 256>>>(out);
}

// round 6
// speedup vs baseline: 2.0518x; 1.0312x over previous
#include <cuda_runtime.h>
#include <cuda_bf16.h>
#include <math.h>
#include <cstdint>

#define NB 1024
#define ND 256
#define NR 16384
#define NW 64
#define NSPLIT 32
#define ADDS 4
#define EPSF 1e-16f
#define KCAT 768

// ---------------- scratch (no allocations allowed) ----------------
__device__ float g_sim[(size_t)NB * NR];   // beta*sim logits, then a (in place)
__device__ float g_pl [(size_t)NB * NR];   // p logits (raw fp32)
__device__ float g_v  [NB * NW];
__device__ float g_vn [NB];
__device__ float g_beta[NB];
__device__ float g_gamma[NB];
__device__ float g_mn [NR];
__device__ float g_part[(size_t)NSPLIT * NB * NW];
__device__ float g_addp[(size_t)ADDS * NR * NW];
__device__ float g_erp [(size_t)ADDS * NR];
__device__ float g_pmx [NB];
__device__ float g_pinv[NB];
__device__ __nv_bfloat16 g_xcat[(size_t)NB * KCAT];   // [x_hi | x_lo | x_hi]
__device__ __nv_bfloat16 g_wcat[(size_t)NR * KCAT];   // [W_hi | W_hi | W_lo] (transposed)
__device__ __nv_bfloat16 g_vh  [NB * NW];
__device__ __nv_bfloat16 g_memh[NR * NW];
__device__ __nv_bfloat16 g_m2h[(size_t)NW * NR];      // mem2^T hi  [w][r]
__device__ __nv_bfloat16 g_m2l[(size_t)NW * NR];      // mem2^T lo  [w][r]

__device__ __forceinline__ float softplus_f(float z) {
    return z > 0.f ? z + log1pf(expf(-z)) : log1pf(expf(z));
}
__device__ __forceinline__ uint32_t smem_u32(const void* p) {
    uint32_t a;
    asm("{ .reg .u64 t; cvta.to.shared.u64 t, %1; cvt.u32.u64 %0, t; }" : "=r"(a) : "l"(p));
    return a;
}
__device__ __forceinline__ void ldsm_x4(uint32_t& r0, uint32_t& r1, uint32_t& r2, uint32_t& r3,
                                        uint32_t addr) {
    asm volatile("ldmatrix.sync.aligned.m8n8.x4.shared.b16 {%0, %1, %2, %3}, [%4];"
                 : "=r"(r0), "=r"(r1), "=r"(r2), "=r"(r3) : "r"(addr));
}
__device__ __forceinline__ void mma16816(float* d, const uint32_t* a, const uint32_t* b) {
    asm volatile(
        "mma.sync.aligned.m16n8k16.row.col.f32.bf16.bf16.f32 "
        "{%0, %1, %2, %3}, {%4, %5, %6, %7}, {%8, %9}, {%0, %1, %2, %3};"
        : "+f"(d[0]), "+f"(d[1]), "+f"(d[2]), "+f"(d[3])
        : "r"(a[0]), "r"(a[1]), "r"(a[2]), "r"(a[3]), "r"(b[0]), "r"(b[1]));
}
__device__ __forceinline__ void cp_async16(uint32_t saddr, const void* g) {
    asm volatile("cp.async.cg.shared.global [%0], [%1], 16;" :: "r"(saddr), "l"(g));
}
#define CP_COMMIT() asm volatile("cp.async.commit_group;" ::: "memory")
#define CP_WAIT(n)  asm volatile("cp.async.wait_group %0;" :: "n"(n) : "memory")

// block reductions for 1024 threads (32 warps)
__device__ __forceinline__ float blk_max(float v, float* red) {
    int lane = threadIdx.x & 31, w = threadIdx.x >> 5;
    #pragma unroll
    for (int o = 16; o; o >>= 1) v = fmaxf(v, __shfl_xor_sync(0xffffffffu, v, o));
    if (!lane) red[w] = v;
    __syncthreads();
    if (w == 0) {
        v = red[lane];
        #pragma unroll
        for (int o = 16; o; o >>= 1) v = fmaxf(v, __shfl_xor_sync(0xffffffffu, v, o));
        if (!lane) red[0] = v;
    }
    __syncthreads();
    v = red[0];
    __syncthreads();
    return v;
}
__device__ __forceinline__ float blk_sum(float v, float* red) {
    int lane = threadIdx.x & 31, w = threadIdx.x >> 5;
    #pragma unroll
    for (int o = 16; o; o >>= 1) v += __shfl_xor_sync(0xffffffffu, v, o);
    if (!lane) red[w] = v;
    __syncthreads();
    if (w == 0) {
        v = red[lane];
        #pragma unroll
        for (int o = 16; o; o >>= 1) v += __shfl_xor_sync(0xffffffffu, v, o);
        if (!lane) red[0] = v;
    }
    __syncthreads();
    v = red[0];
    __syncthreads();
    return v;
}

// ---------------- K1: controller heads ----------------
__global__ void heads_kernel(const float* __restrict__ x,
                             const float* __restrict__ Wv, const float* __restrict__ bv,
                             const float* __restrict__ Wb, const float* __restrict__ bb,
                             const float* __restrict__ Wg, const float* __restrict__ bg) {
    int b = blockIdx.x, t = threadIdx.x;        // 64 threads
    __shared__ float xs[ND];
    __shared__ float red[64];
    for (int i = t; i < ND; i += 64) xs[i] = x[b * ND + i];
    __syncthreads();

    float acc = 0.f;
    #pragma unroll 8
    for (int d = 0; d < ND; ++d) acc = fmaf(xs[d], Wv[d * NW + t], acc);
    float pb = 0.f, pg = 0.f;
    for (int d = t; d < ND; d += 64) {
        pb = fmaf(xs[d], Wb[d], pb);
        pg = fmaf(xs[d], Wg[d], pg);
    }
    float v = acc + bv[t];
    g_v[b * NW + t] = v;
    g_vh[b * NW + t] = __float2bfloat16(v);

    red[t] = v * v; __syncthreads();
    for (int s = 32; s > 0; s >>= 1) { if (t < s) red[t] += red[t + s]; __syncthreads(); }
    if (t == 0) g_vn[b] = sqrtf(red[0]);
    __syncthreads();

    red[t] = pb; __syncthreads();
    for (int s = 32; s > 0; s >>= 1) { if (t < s) red[t] += red[t + s]; __syncthreads(); }
    if (t == 0) g_beta[b] = softplus_f(red[0] + bb[0]);
    __syncthreads();

    red[t] = pg; __syncthreads();
    for (int s = 32; s > 0; s >>= 1) { if (t < s) red[t] += red[t + s]; __syncthreads(); }
    if (t == 0) g_gamma[b] = 1.f + softplus_f(red[0] + bg[0]);
}

// ---------------- K0: memory row norms ----------------
__global__ void mn_kernel(const float* __restrict__ mem) {
    int r = blockIdx.x * blockDim.x + threadIdx.x;
    if (r >= NR) return;
    const float4* m4 = (const float4*)(mem + (size_t)r * NW);
    float s = 0.f;
    #pragma unroll
    for (int i = 0; i < NW / 4; ++i) {
        float4 t4 = m4[i];
        s += t4.x * t4.x + t4.y * t4.y + t4.z * t4.z + t4.w * t4.w;
    }
    g_mn[r] = sqrtf(s);
}

// ---------------- prep: mem -> bf16 ----------------
__global__ void memh_kernel(const float* __restrict__ mem) {
    int i = blockIdx.x * 256 + threadIdx.x;
    float4 f = *(const float4*)&mem[(size_t)i * 4];
    __nv_bfloat162 h0 = __float22bfloat162_rn(make_float2(f.x, f.y));
    __nv_bfloat162 h1 = __float22bfloat162_rn(make_float2(f.z, f.w));
    *(__nv_bfloat162*)&g_memh[(size_t)i * 4]     = h0;
    *(__nv_bfloat162*)&g_memh[(size_t)i * 4 + 2] = h1;
}

// ---------------- K2: sim via HMMA bf16 ----------------
#define SLS 72
__global__ void __launch_bounds__(256, 2)
sim_tc_kernel() {
    __shared__ __nv_bfloat16 As[128][SLS];
    __shared__ __nv_bfloat16 Bs[128][SLS];
    int tid = threadIdx.x;
    int lane = tid & 31, wid = tid >> 5;
    int n0 = blockIdx.x * 128;    // r
    int b0 = blockIdx.y * 128;    // b
    int wm0 = (wid & 1) * 64;
    int wn0 = (wid >> 1) * 32;

    #pragma unroll
    for (int i = 0; i < 4; ++i) {
        int q = tid + i * 256;
        int row = q >> 3, seg = (q & 7) * 8;
        *(uint4*)&As[row][seg] = *(const uint4*)&g_vh[(size_t)(b0 + row) * NW + seg];
        *(uint4*)&Bs[row][seg] = *(const uint4*)&g_memh[(size_t)(n0 + row) * NW + seg];
    }
    __syncthreads();

    float d[4][4][4] = {};
    uint32_t as_base = smem_u32(&As[0][0]);
    uint32_t bs_base = smem_u32(&Bs[0][0]);
    int a_row = wm0 + (lane & 15);
    int a_kof = (lane >> 4) * 8;
    int b_rof = ((lane >> 4) * 8) + (lane & 7);
    int b_kof = ((lane >> 3) & 1) * 8;

    #pragma unroll
    for (int ks = 0; ks < 4; ++ks) {
        int k0 = ks * 16;
        uint32_t a[4][4];
        #pragma unroll
        for (int mi = 0; mi < 4; ++mi) {
            uint32_t addr = as_base + ((a_row + mi * 16) * SLS + k0 + a_kof) * 2;
            ldsm_x4(a[mi][0], a[mi][1], a[mi][2], a[mi][3], addr);
        }
        uint32_t bfr[2][4];
        #pragma unroll
        for (int nj = 0; nj < 2; ++nj) {
            uint32_t addr = bs_base + ((wn0 + nj * 16 + b_rof) * SLS + k0 + b_kof) * 2;
            ldsm_x4(bfr[nj][0], bfr[nj][1], bfr[nj][2], bfr[nj][3], addr);
        }
        #pragma unroll
        for (int mi = 0; mi < 4; ++mi)
            #pragma unroll
            for (int ni = 0; ni < 4; ++ni)
                mma16816(d[mi][ni], a[mi], &bfr[ni >> 1][(ni & 1) * 2]);
    }

    int gr = lane >> 2, gc = (lane & 3) * 2;
    #pragma unroll
    for (int mi = 0; mi < 4; ++mi) {
        int bi0 = b0 + wm0 + mi * 16 + gr;
        float s0 = g_beta[bi0] , n0v = g_vn[bi0];
        float s1 = g_beta[bi0 + 8], n1v = g_vn[bi0 + 8];
        #pragma unroll
        for (int ni = 0; ni < 4; ++ni) {
            int c = n0 + wn0 + ni * 8 + gc;
            float m0 = g_mn[c], m1 = g_mn[c + 1];
            *(float2*)&g_sim[(size_t)bi0 * NR + c] = make_float2(
                s0 * d[mi][ni][0] / (n0v * m0 + EPSF),
                s0 * d[mi][ni][1] / (n0v * m1 + EPSF));
            *(float2*)&g_sim[(size_t)(bi0 + 8) * NR + c] = make_float2(
                s1 * d[mi][ni][2] / (n1v * m0 + EPSF),
                s1 * d[mi][ni][3] / (n1v * m1 + EPSF));
        }
    }
}

// ---------------- K3: softmax -> conv(K=3) -> pow(gamma) -> renorm ----------------
__global__ void wa_kernel(const float* __restrict__ conv_k, const float* __restrict__ conv_b) {
    extern __shared__ float ws[];
    __shared__ float red[32];
    int b = blockIdx.x, t = threadIdx.x;
    float* row = g_sim + (size_t)b * NR;

    float loc[16];
    float mx = -1e30f;
    #pragma unroll
    for (int i = 0; i < 16; ++i) { loc[i] = row[t + i * 1024]; mx = fmaxf(mx, loc[i]); }
    mx = blk_max(mx, red);

    float sum = 0.f;
    #pragma unroll
    for (int i = 0; i < 16; ++i) {
        float e = __expf(loc[i] - mx);
        ws[t + i * 1024] = e;
        sum += e;
    }
    sum = blk_sum(sum, red);
    float inv = 1.f / sum;

    float c0 = conv_k[0], c1 = conv_k[1], c2 = conv_k[2], cb = conv_b[0];
    float gam = g_gamma[b];
    float asum = 0.f;
    #pragma unroll
    for (int i = 0; i < 16; ++i) {
        int r = t + i * 1024;
        float wl = (r > 0)      ? ws[r - 1] : 0.f;
        float wr = (r < NR - 1) ? ws[r + 1] : 0.f;
        float wc = fmaf(wl, c0, fmaf(ws[r], c1, wr * c2)) * inv + cb;
        float a = __powf(wc, gam);
        loc[i] = a; asum += a;
    }
    asum = blk_sum(asum, red);
    float invd = 1.f / (asum + (float)NR * EPSF);

    #pragma unroll
    for (int i = 0; i < 16; ++i) row[t + i * 1024] = loc[i] * invd;
}

// ---------------- K4a: add/erase partials, split over B ----------------
__global__ void add_gemm_split() {
    __shared__ float As[16][68];
    __shared__ float Bs[16][68];
    int r0 = blockIdx.x * 64;
    int split = blockIdx.y;
    int tid = threadIdx.x, tx = tid & 15, ty = tid >> 4;
    float acc[4][4] = {};
    float er[4] = {};

    int kend = (split + 1) * (NB / ADDS);
    for (int k0 = split * (NB / ADDS); k0 < kend; k0 += 16) {
        int kk = tid >> 4, c4 = (tid & 15) << 2;
        *(float4*)&As[kk][c4] = *(const float4*)&g_sim[(size_t)(k0 + kk) * NR + r0 + c4];
        *(float4*)&Bs[kk][c4] = *(const float4*)&g_v[(k0 + kk) * NW + c4];
        __syncthreads();
        #pragma unroll
        for (int k = 0; k < 16; ++k) {
            float4 ra = *(float4*)&As[k][ty * 4];
            float4 rb = *(float4*)&Bs[k][tx * 4];
            float a_[4] = {ra.x, ra.y, ra.z, ra.w};
            float b_[4] = {rb.x, rb.y, rb.z, rb.w};
            er[0] += a_[0]; er[1] += a_[1]; er[2] += a_[2]; er[3] += a_[3];
            #pragma unroll
            for (int i = 0; i < 4; ++i)
                #pragma unroll
                for (int j = 0; j < 4; ++j)
                    acc[i][j] = fmaf(a_[i], b_[j], acc[i][j]);
        }
        __syncthreads();
    }
    #pragma unroll
    for (int i = 0; i < 4; ++i) {
        int r = r0 + ty * 4 + i;
        if (tx == 0) g_erp[(size_t)split * NR + r] = er[i];
        #pragma unroll
        for (int j = 0; j < 4; ++j)
            g_addp[((size_t)split * NR + r) * NW + tx * 4 + j] = acc[i][j];
    }
}

// ---------------- K4b: combine partials -> mem2, transpose + bf16 hi/lo split ---------
__global__ void mem2t_kernel(const float* __restrict__ mem) {
    __shared__ float t[64][65];
    __shared__ float ev[64];
    int r0 = blockIdx.x * 64;
    int tid = threadIdx.x;
    const float invB = 1.f / (float)NB;

    if (tid < 64) {
        float e = 0.f;
        #pragma unroll
        for (int s = 0; s < ADDS; ++s) e += g_erp[(size_t)s * NR + r0 + tid];
        ev[tid] = 1.f - e * invB;
    }
    __syncthreads();

    #pragma unroll
    for (int i = 0; i < 16; ++i) {
        int q = tid + i * 256;
        int r = q >> 6, w = q & 63;
        float ad = 0.f;
        #pragma unroll
        for (int s = 0; s < ADDS; ++s) ad += g_addp[((size_t)s * NR + r0 + r) * NW + w];
        t[r][w] = mem[(size_t)(r0 + r) * NW + w] * ev[r] + ad * invB;
    }
    __syncthreads();

    #pragma unroll
    for (int i = 0; i < 16; ++i) {
        int q = tid + i * 256;
        int w = q >> 6, r = q & 63;
        float f = t[r][w];
        __nv_bfloat16 h = __float2bfloat16(f);
        __nv_bfloat16 l = __float2bfloat16(f - __bfloat162float(h));
        g_m2h[(size_t)w * NR + r0 + r] = h;
        g_m2l[(size_t)w * NR + r0 + r] = l;
    }
}

// ---------------- prep: xcat = [x_hi | x_lo | x_hi] ----------------
__global__ void xcat_kernel(const float* __restrict__ x) {
    int i = blockIdx.x * 256 + threadIdx.x;
    int b = i >> 8, k = i & 255;
    float f = x[i];
    __nv_bfloat16 h = __float2bfloat16(f);
    __nv_bfloat16 l = __float2bfloat16(f - __bfloat162float(h));
    g_xcat[(size_t)b * KCAT + k]       = h;
    g_xcat[(size_t)b * KCAT + 256 + k] = l;
    g_xcat[(size_t)b * KCAT + 512 + k] = h;
}

// ---------------- prep: wcat ----------------
__global__ void wcat_kernel(const float* __restrict__ Wp) {
    __shared__ float t[32][33];
    int n0 = blockIdx.x * 32, k0 = blockIdx.y * 32;
    int tx = threadIdx.x, ty = threadIdx.y;   // (32, 8)
    #pragma unroll
    for (int i = 0; i < 4; ++i)
        t[ty + 8 * i][tx] = Wp[(size_t)(k0 + ty + 8 * i) * NR + n0 + tx];
    __syncthreads();
    #pragma unroll
    for (int i = 0; i < 4; ++i) {
        int row = ty + 8 * i;
        float f = t[tx][row];
        __nv_bfloat16 h = __float2bfloat16(f);
        __nv_bfloat16 l = __float2bfloat16(f - __bfloat162float(h));
        size_t base = (size_t)(n0 + row) * KCAT + k0 + tx;
        g_wcat[base]       = h;
        g_wcat[base + 256] = h;
        g_wcat[base + 512] = l;
    }
}

// ---------------- K5: p logits, 128x256 CTA tile, cp.async 2-stage ----------------
#define PLS 40
#define PLK (KCAT / 32)
#define PL_ABUF (128 * PLS)
#define PL_BBUF (256 * PLS)

__global__ void __launch_bounds__(512, 1)
pl_mma_kernel(const float* __restrict__ bp) {
    extern __shared__ __nv_bfloat16 sm[];
    __nv_bfloat16* As = sm;                       // [2][128][PLS]
    __nv_bfloat16* Bs = sm + 2 * PL_ABUF;         // [2][256][PLS]
    int tid = threadIdx.x;
    int lane = tid & 31, wid = tid >> 5;          // 16 warps
    int n0 = blockIdx.x * 256;
    int b0 = blockIdx.y * 128;
    int wm0 = (wid & 3) * 32;
    int wn0 = (wid >> 2) * 64;

    uint32_t asb = smem_u32(As), bsb = smem_u32(Bs);
    const uint32_t abufB = PL_ABUF * 2, bbufB = PL_BBUF * 2;

    // load slots
    int arow = tid >> 2, aseg = (tid & 3) * 8;          // 512 uint4 -> 1/thread
    int brow0 = tid >> 2, bseg0 = (tid & 3) * 8;        // B slot 0
    int brow1 = (tid + 512) >> 2, bseg1 = (tid & 3) * 8; // B slot 1

    uint32_t a_sa = asb + (arow * PLS + aseg) * 2;
    uint32_t b_sa0 = bsb + (brow0 * PLS + bseg0) * 2;
    uint32_t b_sa1 = bsb + (brow1 * PLS + bseg1) * 2;
    const __nv_bfloat16* a_g = &g_xcat[(size_t)(b0 + arow) * KCAT + aseg];
    const __nv_bfloat16* b_g0 = &g_wcat[(size_t)(n0 + brow0) * KCAT + bseg0];
    const __nv_bfloat16* b_g1 = &g_wcat[(size_t)(n0 + brow1) * KCAT + bseg1];

    // prologue: chunk 0 -> buf 0
    cp_async16(a_sa, a_g);
    cp_async16(b_sa0, b_g0);
    cp_async16(b_sa1, b_g1);
    CP_COMMIT();

    float acc[2][8][4] = {};
    int a_row = wm0 + (lane & 15);
    int a_kof = (lane >> 4) * 8;
    int b_rof = ((lane >> 4) * 8) + (lane & 7);
    int b_kof = ((lane >> 3) & 1) * 8;

    for (int kc = 0; kc < PLK; ++kc) {
        int cur = kc & 1;
        if (kc + 1 < PLK) {
            int nxt = cur ^ 1;
            int ko = (kc + 1) * 32;
            cp_async16(a_sa + nxt * abufB, a_g + ko);
            cp_async16(b_sa0 + nxt * bbufB, b_g0 + ko);
            cp_async16(b_sa1 + nxt * bbufB, b_g1 + ko);
            CP_COMMIT();
            CP_WAIT(1);
        } else {
            CP_WAIT(0);
        }
        __syncthreads();

        uint32_t abase = asb + cur * abufB;
        uint32_t bbase = bsb + cur * bbufB;
        #pragma unroll
        for (int ks = 0; ks < 2; ++ks) {
            int k0 = ks * 16;
            uint32_t a[2][4];
            #pragma unroll
            for (int mi = 0; mi < 2; ++mi) {
                uint32_t addr = abase + ((a_row + mi * 16) * PLS + k0 + a_kof) * 2;
                ldsm_x4(a[mi][0], a[mi][1], a[mi][2], a[mi][3], addr);
            }
            uint32_t bfr[4][4];
            #pragma unroll
            for (int nj = 0; nj < 4; ++nj) {
                uint32_t addr = bbase + ((wn0 + nj * 16 + b_rof) * PLS + k0 + b_kof) * 2;
                ldsm_x4(bfr[nj][0], bfr[nj][1], bfr[nj][2], bfr[nj][3], addr);
            }
            #pragma unroll
            for (int mi = 0; mi < 2; ++mi)
                #pragma unroll
                for (int nj = 0; nj < 4; ++nj) {
                    mma16816(acc[mi][nj * 2],     a[mi], &bfr[nj][0]);
                    mma16816(acc[mi][nj * 2 + 1], a[mi], &bfr[nj][2]);
                }
        }
        __syncthreads();
    }

    // epilogue
    int gr = lane >> 2, gc = (lane & 3) * 2;
    #pragma unroll
    for (int mi = 0; mi < 2; ++mi) {
        int r1 = b0 + wm0 + mi * 16 + gr;
        #pragma unroll
        for (int j = 0; j < 8; ++j) {
            int c = n0 + wn0 + j * 8 + gc;
            float bpx = bp[c], bpy = bp[c + 1];
            *(float2*)&g_pl[(size_t)r1 * NR + c] =
                make_float2(acc[mi][j][0] + bpx, acc[mi][j][1] + bpy);
            *(float2*)&g_pl[(size_t)(r1 + 8) * NR + c] =
                make_float2(acc[mi][j][2] + bpx, acc[mi][j][3] + bpy);
        }
    }
}

// ---------------- K6: per-row softmax stats for p ----------------
__global__ void pstats_kernel() {
    __shared__ float red[32];
    int b = blockIdx.x, t = threadIdx.x;
    const float* row = g_pl + (size_t)b * NR;

    float loc[16];
    float mx = -1e30f;
    #pragma unroll
    for (int i = 0; i < 16; ++i) { loc[i] = row[t + i * 1024]; mx = fmaxf(mx, loc[i]); }
    mx = blk_max(mx, red);

    float sum = 0.f;
    #pragma unroll
    for (int i = 0; i < 16; ++i) sum += __expf(loc[i] - mx);
    sum = blk_sum(sum, red);

    if (t == 0) { g_pmx[b] = mx; g_pinv[b] = 1.f / sum; }
}

// ---------------- K7: out = softmax(pl) @ mem2 via HMMA hi/lo split, fused exp -------
// D[b][w] = sum_r e[b][r] * m2T[w][r]; 3 terms: ehi*mhi + elo*mhi + ehi*mlo.
#define OLS 72
#define O_EH 0
#define O_EL (128 * OLS)
#define O_MH (256 * OLS)
#define O_ML (320 * OLS)
#define O_SMEM (384 * OLS * 2)

__global__ void __launch_bounds__(256, 2)
out_tc_kernel() {
    extern __shared__ __nv_bfloat16 osm[];
    __nv_bfloat16* EH = osm + O_EH;
    __nv_bfloat16* EL = osm + O_EL;
    __nv_bfloat16* MH = osm + O_MH;
    __nv_bfloat16* ML = osm + O_ML;
    int tid = threadIdx.x;
    int lane = tid & 31, wid = tid >> 5;   // 8 warps, each owns m16 strip
    int split = blockIdx.x;                // 0..NSPLIT-1
    int b0 = blockIdx.y * 128;
    int kbase = split * (NR / NSPLIT);     // 512 per split

    // hoisted softmax stats for the 8 rows this thread loads
    int la = tid >> 4, lb = tid & 15;
    float mxv[8], invv[8];
    #pragma unroll
    for (int i = 0; i < 8; ++i) {
        mxv[i]  = g_pmx[b0 + la + 16 * i];
        invv[i] = g_pinv[b0 + la + 16 * i];
    }
    // mem2 tile slots: 2 uint4 per thread
    int m_row0 = tid >> 3, m_seg0 = (tid & 7) * 8;
    int m_row1 = (tid + 256) >> 3, m_seg1 = (tid & 7) * 8;

    uint32_t ehb = smem_u32(EH), elb = smem_u32(EL);
    uint32_t mhb = smem_u32(MH), mlb = smem_u32(ML);

    float acc[8][4] = {};
    int a_row = wid * 16 + (lane & 15);
    int a_kof = (lane >> 4) * 8;
    int b_rof = ((lane >> 4) * 8) + (lane & 7);
    int b_kof = ((lane >> 3) & 1) * 8;

    for (int kg = kbase; kg < kbase + NR / NSPLIT; kg += 64) {
        // loader: exp of logits -> EH/EL
        #pragma unroll
        for (int i = 0; i < 8; ++i) {
            int row = la + 16 * i;
            float4 l4 = *(const float4*)&g_pl[(size_t)(b0 + row) * NR + kg + lb * 4];
            float e0 = __expf(l4.x - mxv[i]) * invv[i];
            float e1 = __expf(l4.y - mxv[i]) * invv[i];
            float e2 = __expf(l4.z - mxv[i]) * invv[i];
            float e3 = __expf(l4.w - mxv[i]) * invv[i];
            __nv_bfloat16 h0 = __float2bfloat16(e0), h1 = __float2bfloat16(e1);
            __nv_bfloat16 h2 = __float2bfloat16(e2), h3 = __float2bfloat16(e3);
            __nv_bfloat16 l0 = __float2bfloat16(e0 - __bfloat162float(h0));
            __nv_bfloat16 l1 = __float2bfloat16(e1 - __bfloat162float(h1));
            __nv_bfloat16 l2 = __float2bfloat16(e2 - __bfloat162float(h2));
            __nv_bfloat16 l3 = __float2bfloat16(e3 - __bfloat162float(h3));
            __nv_bfloat16* eh = &EH[row * OLS + lb * 4];
            __nv_bfloat16* el = &EL[row * OLS + lb * 4];
            eh[0] = h0; eh[1] = h1; eh[2] = h2; eh[3] = h3;
            el[0] = l0; el[1] = l1; el[2] = l2; el[3] = l3;
        }
        // mem2^T tiles
        *(uint4*)&MH[m_row0 * OLS + m_seg0] = *(const uint4*)&g_m2h[(size_t)m_row0 * NR + kg + m_seg0];
        *(uint4*)&MH[m_row1 * OLS + m_seg1] = *(const uint4*)&g_m2h[(size_t)m_row1 * NR + kg + m_seg1];
        *(uint4*)&ML[m_row0 * OLS + m_seg0] = *(const uint4*)&g_m2l[(size_t)m_row0 * NR + kg + m_seg0];
        *(uint4*)&ML[m_row1 * OLS + m_seg1] = *(const uint4*)&g_m2l[(size_t)m_row1 * NR + kg + m_seg1];
        __syncthreads();

        #pragma unroll
        for (int ks = 0; ks < 4; ++ks) {
            int k0 = ks * 16;
            uint32_t ah[4], al[4];
            {
                uint32_t addr = ehb + (a_row * OLS + k0 + a_kof) * 2;
                ldsm_x4(ah[0], ah[1], ah[2], ah[3], addr);
                addr = elb + (a_row * OLS + k0 + a_kof) * 2;
                ldsm_x4(al[0], al[1], al[2], al[3], addr);
            }
            uint32_t bh[4][4], bl[4][4];
            #pragma unroll
            for (int g = 0; g < 4; ++g) {
                uint32_t addr = mhb + ((g * 16 + b_rof) * OLS + k0 + b_kof) * 2;
                ldsm_x4(bh[g][0], bh[g][1], bh[g][2], bh[g][3], addr);
                addr = mlb + ((g * 16 + b_rof) * OLS + k0 + b_kof) * 2;
                ldsm_x4(bl[g][0], bl[g][1], bl[g][2], bl[g][3], addr);
            }
            #pragma unroll
            for (int g = 0; g < 4; ++g) {
                mma16816(acc[g * 2],     ah, &bh[g][0]);
                mma16816(acc[g * 2 + 1], ah, &bh[g][2]);
                mma16816(acc[g * 2],     al, &bh[g][0]);
                mma16816(acc[g * 2 + 1], al, &bh[g][2]);
                mma16816(acc[g * 2],     ah, &bl[g][0]);
                mma16816(acc[g * 2 + 1], ah, &bl[g][2]);
            }
        }
        __syncthreads();
    }

    // write partials
    int gr = lane >> 2, gc = (lane & 3) * 2;
    int r1 = b0 + wid * 16 + gr;
    #pragma unroll
    for (int j = 0; j < 8; ++j) {
        int c = j * 8 + gc;
        *(float2*)&g_part[(size_t)split * (NB * NW) + (size_t)r1 * NW + c] =
            make_float2(acc[j][0], acc[j][1]);
        *(float2*)&g_part[(size_t)split * (NB * NW) + (size_t)(r1 + 8) * NW + c] =
            make_float2(acc[j][2], acc[j][3]);
    }
}

__global__ void out_reduce(float* __restrict__ out) {
    int i = blockIdx.x * blockDim.x + threadIdx.x;
    float s = 0.f;
    #pragma unroll
    for (int p = 0; p < NSPLIT; ++p) s += g_part[(size_t)p * (NB * NW) + i];
    out[i] = s;
}

// ---------------- launch ----------------
extern "C" void kernel_launch(void* const* d_in, const int* in_sizes, int n_in,
                              void* d_out, int out_size) {
    const float* x   = (const float*)d_in[0];
    const float* Wv  = (const float*)d_in[1];
    const float* bv  = (const float*)d_in[2];
    const float* Wb  = (const float*)d_in[3];
    const float* bb  = (const float*)d_in[4];
    const float* Wg  = (const float*)d_in[5];
    const float* bg  = (const float*)d_in[6];
    const float* Wp  = (const float*)d_in[7];
    const float* bp  = (const float*)d_in[8];
    const float* ck  = (const float*)d_in[9];
    const float* cbv = (const float*)d_in[10];
    const float* mem = (const float*)d_in[11];
    float* out = (float*)d_out;
    (void)in_sizes; (void)n_in; (void)out_size;

    const int pl_smem = 2 * (PL_ABUF + PL_BBUF) * 2;
    cudaFuncSetAttribute(wa_kernel, cudaFuncAttributeMaxDynamicSharedMemorySize, NR * 4);
    cudaFuncSetAttribute(pl_mma_kernel, cudaFuncAttributeMaxDynamicSharedMemorySize, pl_smem);
    cudaFuncSetAttribute(out_tc_kernel, cudaFuncAttributeMaxDynamicSharedMemorySize, O_SMEM);

    heads_kernel<<<NB, 64>>>(x, Wv, bv, Wb, bb, Wg, bg);
    mn_kernel<<<NR / 256, 256>>>(mem);
    memh_kernel<<<NR * NW / 4 / 256, 256>>>(mem);
    xcat_kernel<<<NB * ND / 256, 256>>>(x);
    wcat_kernel<<<dim3(NR / 32, ND / 32), dim3(32, 8)>>>(Wp);
    sim_tc_kernel<<<dim3(NR / 128, NB / 128), 256>>>();
    wa_kernel<<<NB, 1024, NR * 4>>>(ck, cbv);
    add_gemm_split<<<dim3(NR / 64, ADDS), 256>>>();
    mem2t_kernel<<<NR / 64, 256>>>(mem);
    pl_mma_kernel<<<dim3(NR / 256, NB / 128), 512, pl_smem>>>(bp);
    pstats_kernel<<<NB, 1024>>>();
    out_tc_kernel<<<dim3(NSPLIT, NB / 128), 256, O_SMEM>>>();
    out_reduce<<<NB * NW / 256, 256>>>(out);
}

// round 7
// speedup vs baseline: 2.5484x; 1.2421x over previous
#include <cuda_runtime.h>
#include <cuda_bf16.h>
#include <math.h>
#include <cstdint>

#define NB 1024
#define ND 256
#define NR 16384
#define NW 64
#define NSPLIT 32
#define EPSF 1e-16f
#define KCAT 768

// ---------------- scratch (no allocations allowed) ----------------
__device__ float g_sim[(size_t)NB * NR];   // beta*sim logits, then a (in place)
__device__ float g_pl [(size_t)NB * NR];   // p logits (raw fp32)
__device__ float g_v  [NB * NW];
__device__ float g_vn [NB];
__device__ float g_beta[NB];
__device__ float g_gamma[NB];
__device__ float g_mn [NR];
__device__ float g_part[(size_t)NSPLIT * NB * NW];
__device__ float g_add[(size_t)NR * NW];
__device__ float g_er [NR];
__device__ float g_pmx [NB];
__device__ float g_pinv[NB];
__device__ __nv_bfloat16 g_xcat[(size_t)NB * KCAT];   // [x_hi | x_lo | x_hi]
__device__ __nv_bfloat16 g_wcat[(size_t)NR * KCAT];   // [W_hi | W_hi | W_lo] (transposed)
__device__ __nv_bfloat16 g_vh  [NB * NW];
__device__ __nv_bfloat16 g_memh[NR * NW];
__device__ __nv_bfloat16 g_m2h[(size_t)NW * NR];      // mem2^T hi  [w][r]
__device__ __nv_bfloat16 g_m2l[(size_t)NW * NR];      // mem2^T lo  [w][r]

__device__ __forceinline__ float softplus_f(float z) {
    return z > 0.f ? z + log1pf(expf(-z)) : log1pf(expf(z));
}
__device__ __forceinline__ uint32_t smem_u32(const void* p) {
    uint32_t a;
    asm("{ .reg .u64 t; cvta.to.shared.u64 t, %1; cvt.u32.u64 %0, t; }" : "=r"(a) : "l"(p));
    return a;
}
__device__ __forceinline__ void ldsm_x4(uint32_t& r0, uint32_t& r1, uint32_t& r2, uint32_t& r3,
                                        uint32_t addr) {
    asm volatile("ldmatrix.sync.aligned.m8n8.x4.shared.b16 {%0, %1, %2, %3}, [%4];"
                 : "=r"(r0), "=r"(r1), "=r"(r2), "=r"(r3) : "r"(addr));
}
__device__ __forceinline__ void ldsm_x4t(uint32_t& r0, uint32_t& r1, uint32_t& r2, uint32_t& r3,
                                         uint32_t addr) {
    asm volatile("ldmatrix.sync.aligned.m8n8.x4.trans.shared.b16 {%0, %1, %2, %3}, [%4];"
                 : "=r"(r0), "=r"(r1), "=r"(r2), "=r"(r3) : "r"(addr));
}
__device__ __forceinline__ void mma16816(float* d, const uint32_t* a, const uint32_t* b) {
    asm volatile(
        "mma.sync.aligned.m16n8k16.row.col.f32.bf16.bf16.f32 "
        "{%0, %1, %2, %3}, {%4, %5, %6, %7}, {%8, %9}, {%0, %1, %2, %3};"
        : "+f"(d[0]), "+f"(d[1]), "+f"(d[2]), "+f"(d[3])
        : "r"(a[0]), "r"(a[1]), "r"(a[2]), "r"(a[3]), "r"(b[0]), "r"(b[1]));
}
__device__ __forceinline__ void cp_async16(uint32_t saddr, const void* g) {
    asm volatile("cp.async.cg.shared.global [%0], [%1], 16;" :: "r"(saddr), "l"(g));
}
#define CP_COMMIT() asm volatile("cp.async.commit_group;" ::: "memory")
#define CP_WAIT(n)  asm volatile("cp.async.wait_group %0;" :: "n"(n) : "memory")

// block reductions for 1024 threads (32 warps)
__device__ __forceinline__ float blk_max(float v, float* red) {
    int lane = threadIdx.x & 31, w = threadIdx.x >> 5;
    #pragma unroll
    for (int o = 16; o; o >>= 1) v = fmaxf(v, __shfl_xor_sync(0xffffffffu, v, o));
    if (!lane) red[w] = v;
    __syncthreads();
    if (w == 0) {
        v = red[lane];
        #pragma unroll
        for (int o = 16; o; o >>= 1) v = fmaxf(v, __shfl_xor_sync(0xffffffffu, v, o));
        if (!lane) red[0] = v;
    }
    __syncthreads();
    v = red[0];
    __syncthreads();
    return v;
}
__device__ __forceinline__ float blk_sum(float v, float* red) {
    int lane = threadIdx.x & 31, w = threadIdx.x >> 5;
    #pragma unroll
    for (int o = 16; o; o >>= 1) v += __shfl_xor_sync(0xffffffffu, v, o);
    if (!lane) red[w] = v;
    __syncthreads();
    if (w == 0) {
        v = red[lane];
        #pragma unroll
        for (int o = 16; o; o >>= 1) v += __shfl_xor_sync(0xffffffffu, v, o);
        if (!lane) red[0] = v;
    }
    __syncthreads();
    v = red[0];
    __syncthreads();
    return v;
}

// ---------------- K1: controller heads ----------------
__global__ void heads_kernel(const float* __restrict__ x,
                             const float* __restrict__ Wv, const float* __restrict__ bv,
                             const float* __restrict__ Wb, const float* __restrict__ bb,
                             const float* __restrict__ Wg, const float* __restrict__ bg) {
    int b = blockIdx.x, t = threadIdx.x;        // 64 threads
    __shared__ float xs[ND];
    __shared__ float red[64];
    for (int i = t; i < ND; i += 64) xs[i] = x[b * ND + i];
    __syncthreads();

    float acc = 0.f;
    #pragma unroll 8
    for (int d = 0; d < ND; ++d) acc = fmaf(xs[d], Wv[d * NW + t], acc);
    float pb = 0.f, pg = 0.f;
    for (int d = t; d < ND; d += 64) {
        pb = fmaf(xs[d], Wb[d], pb);
        pg = fmaf(xs[d], Wg[d], pg);
    }
    float v = acc + bv[t];
    g_v[b * NW + t] = v;
    g_vh[b * NW + t] = __float2bfloat16(v);

    red[t] = v * v; __syncthreads();
    for (int s = 32; s > 0; s >>= 1) { if (t < s) red[t] += red[t + s]; __syncthreads(); }
    if (t == 0) g_vn[b] = sqrtf(red[0]);
    __syncthreads();

    red[t] = pb; __syncthreads();
    for (int s = 32; s > 0; s >>= 1) { if (t < s) red[t] += red[t + s]; __syncthreads(); }
    if (t == 0) g_beta[b] = softplus_f(red[0] + bb[0]);
    __syncthreads();

    red[t] = pg; __syncthreads();
    for (int s = 32; s > 0; s >>= 1) { if (t < s) red[t] += red[t + s]; __syncthreads(); }
    if (t == 0) g_gamma[b] = 1.f + softplus_f(red[0] + bg[0]);
}

// ---------------- K0: memory row norms ----------------
__global__ void mn_kernel(const float* __restrict__ mem) {
    int r = blockIdx.x * blockDim.x + threadIdx.x;
    if (r >= NR) return;
    const float4* m4 = (const float4*)(mem + (size_t)r * NW);
    float s = 0.f;
    #pragma unroll
    for (int i = 0; i < NW / 4; ++i) {
        float4 t4 = m4[i];
        s += t4.x * t4.x + t4.y * t4.y + t4.z * t4.z + t4.w * t4.w;
    }
    g_mn[r] = sqrtf(s);
}

// ---------------- prep: mem -> bf16 ----------------
__global__ void memh_kernel(const float* __restrict__ mem) {
    int i = blockIdx.x * 256 + threadIdx.x;
    float4 f = *(const float4*)&mem[(size_t)i * 4];
    __nv_bfloat162 h0 = __float22bfloat162_rn(make_float2(f.x, f.y));
    __nv_bfloat162 h1 = __float22bfloat162_rn(make_float2(f.z, f.w));
    *(__nv_bfloat162*)&g_memh[(size_t)i * 4]     = h0;
    *(__nv_bfloat162*)&g_memh[(size_t)i * 4 + 2] = h1;
}

// ---------------- K2: sim via HMMA bf16 ----------------
#define SLS 72
__global__ void __launch_bounds__(256, 2)
sim_tc_kernel() {
    __shared__ __nv_bfloat16 As[128][SLS];
    __shared__ __nv_bfloat16 Bs[128][SLS];
    int tid = threadIdx.x;
    int lane = tid & 31, wid = tid >> 5;
    int n0 = blockIdx.x * 128;    // r
    int b0 = blockIdx.y * 128;    // b
    int wm0 = (wid & 1) * 64;
    int wn0 = (wid >> 1) * 32;

    #pragma unroll
    for (int i = 0; i < 4; ++i) {
        int q = tid + i * 256;
        int row = q >> 3, seg = (q & 7) * 8;
        *(uint4*)&As[row][seg] = *(const uint4*)&g_vh[(size_t)(b0 + row) * NW + seg];
        *(uint4*)&Bs[row][seg] = *(const uint4*)&g_memh[(size_t)(n0 + row) * NW + seg];
    }
    __syncthreads();

    float d[4][4][4] = {};
    uint32_t as_base = smem_u32(&As[0][0]);
    uint32_t bs_base = smem_u32(&Bs[0][0]);
    int a_row = wm0 + (lane & 15);
    int a_kof = (lane >> 4) * 8;
    int b_rof = ((lane >> 4) * 8) + (lane & 7);
    int b_kof = ((lane >> 3) & 1) * 8;

    #pragma unroll
    for (int ks = 0; ks < 4; ++ks) {
        int k0 = ks * 16;
        uint32_t a[4][4];
        #pragma unroll
        for (int mi = 0; mi < 4; ++mi) {
            uint32_t addr = as_base + ((a_row + mi * 16) * SLS + k0 + a_kof) * 2;
            ldsm_x4(a[mi][0], a[mi][1], a[mi][2], a[mi][3], addr);
        }
        uint32_t bfr[2][4];
        #pragma unroll
        for (int nj = 0; nj < 2; ++nj) {
            uint32_t addr = bs_base + ((wn0 + nj * 16 + b_rof) * SLS + k0 + b_kof) * 2;
            ldsm_x4(bfr[nj][0], bfr[nj][1], bfr[nj][2], bfr[nj][3], addr);
        }
        #pragma unroll
        for (int mi = 0; mi < 4; ++mi)
            #pragma unroll
            for (int ni = 0; ni < 4; ++ni)
                mma16816(d[mi][ni], a[mi], &bfr[ni >> 1][(ni & 1) * 2]);
    }

    int gr = lane >> 2, gc = (lane & 3) * 2;
    #pragma unroll
    for (int mi = 0; mi < 4; ++mi) {
        int bi0 = b0 + wm0 + mi * 16 + gr;
        float s0 = g_beta[bi0] , n0v = g_vn[bi0];
        float s1 = g_beta[bi0 + 8], n1v = g_vn[bi0 + 8];
        #pragma unroll
        for (int ni = 0; ni < 4; ++ni) {
            int c = n0 + wn0 + ni * 8 + gc;
            float m0 = g_mn[c], m1 = g_mn[c + 1];
            *(float2*)&g_sim[(size_t)bi0 * NR + c] = make_float2(
                s0 * d[mi][ni][0] / (n0v * m0 + EPSF),
                s0 * d[mi][ni][1] / (n0v * m1 + EPSF));
            *(float2*)&g_sim[(size_t)(bi0 + 8) * NR + c] = make_float2(
                s1 * d[mi][ni][2] / (n1v * m0 + EPSF),
                s1 * d[mi][ni][3] / (n1v * m1 + EPSF));
        }
    }
}

// ---------------- K3: softmax -> conv(K=3) -> pow(gamma) -> renorm (float4) ---------
__global__ void wa_kernel(const float* __restrict__ conv_k, const float* __restrict__ conv_b) {
    extern __shared__ float ws[];
    __shared__ float red[32];
    int b = blockIdx.x, t = threadIdx.x;   // 1024 threads
    float* row = g_sim + (size_t)b * NR;

    float4 loc[4];
    float mx = -1e30f;
    #pragma unroll
    for (int i = 0; i < 4; ++i) {
        loc[i] = *(const float4*)&row[i * 4096 + t * 4];
        mx = fmaxf(mx, fmaxf(fmaxf(loc[i].x, loc[i].y), fmaxf(loc[i].z, loc[i].w)));
    }
    mx = blk_max(mx, red);

    float sum = 0.f;
    #pragma unroll
    for (int i = 0; i < 4; ++i) {
        float4 e;
        e.x = __expf(loc[i].x - mx); e.y = __expf(loc[i].y - mx);
        e.z = __expf(loc[i].z - mx); e.w = __expf(loc[i].w - mx);
        *(float4*)&ws[i * 4096 + t * 4] = e;
        sum += e.x + e.y + e.z + e.w;
    }
    sum = blk_sum(sum, red);
    float inv = 1.f / sum;

    float c0 = conv_k[0], c1 = conv_k[1], c2 = conv_k[2], cb = conv_b[0];
    float gam = g_gamma[b];
    float la[16];
    float asum = 0.f;
    #pragma unroll
    for (int i = 0; i < 4; ++i) {
        int base = i * 4096 + t * 4;
        #pragma unroll
        for (int c = 0; c < 4; ++c) {
            int r = base + c;
            float wl = (r > 0)      ? ws[r - 1] : 0.f;
            float wr = (r < NR - 1) ? ws[r + 1] : 0.f;
            float wc = fmaf(wl, c0, fmaf(ws[r], c1, wr * c2)) * inv + cb;
            float a = __powf(wc, gam);
            la[i * 4 + c] = a; asum += a;
        }
    }
    asum = blk_sum(asum, red);
    float invd = 1.f / (asum + (float)NR * EPSF);

    #pragma unroll
    for (int i = 0; i < 4; ++i) {
        float4 o;
        o.x = la[i * 4 + 0] * invd; o.y = la[i * 4 + 1] * invd;
        o.z = la[i * 4 + 2] * invd; o.w = la[i * 4 + 3] * invd;
        *(float4*)&row[i * 4096 + t * 4] = o;
    }
}

// ---------------- K4a: add/erase via HMMA bf16 (ldmatrix.trans) ----------------
// g_add[r][w] = sum_b a[b][r] v[b][w]; g_er[r] = sum_b a[b][r] (raw sums).
#define ATS 72
__global__ void __launch_bounds__(128, 4)
add_tc_kernel() {
    __shared__ __nv_bfloat16 As[128][ATS];   // [b-local][r-local 64]
    __shared__ __nv_bfloat16 Vs[128][ATS];   // [b-local][w 64]
    int tid = threadIdx.x, lane = tid & 31, wid = tid >> 5;   // 4 warps
    int r0 = blockIdx.x * 64;
    float acc[8][4] = {};
    float acce[4] = {};
    uint32_t onesf[2] = {0x3F803F80u, 0x3F803F80u};
    uint32_t asb = smem_u32(&As[0][0]), vsb = smem_u32(&Vs[0][0]);
    int m0 = wid * 16;
    int lrow = (lane & 7) + ((lane & 16) >> 1);
    int lcol = lane & 8;

    for (int kb = 0; kb < NB; kb += 128) {
        // a tile: 128 x 64 fp32 -> bf16 (trans-ready [b][r] layout)
        #pragma unroll
        for (int i = 0; i < 16; ++i) {
            int q = tid + i * 128;
            int kk = q >> 4, c = (q & 15) * 4;
            float4 f = *(const float4*)&g_sim[(size_t)(kb + kk) * NR + r0 + c];
            *(__nv_bfloat162*)&As[kk][c]     = __float22bfloat162_rn(make_float2(f.x, f.y));
            *(__nv_bfloat162*)&As[kk][c + 2] = __float22bfloat162_rn(make_float2(f.z, f.w));
        }
        // v tile: 128 x 64 bf16
        #pragma unroll
        for (int i = 0; i < 8; ++i) {
            int q = tid + i * 128;
            int kk = q >> 3, c = (q & 7) * 8;
            *(uint4*)&Vs[kk][c] = *(const uint4*)&g_vh[(kb + kk) * NW + c];
        }
        __syncthreads();

        #pragma unroll
        for (int ks = 0; ks < 8; ++ks) {
            int k0 = ks * 16;
            uint32_t a[4];
            ldsm_x4t(a[0], a[1], a[2], a[3],
                     asb + ((k0 + lrow) * ATS + m0 + lcol) * 2);
            uint32_t bfr[4][4];
            #pragma unroll
            for (int nj = 0; nj < 4; ++nj)
                ldsm_x4t(bfr[nj][0], bfr[nj][1], bfr[nj][2], bfr[nj][3],
                         vsb + ((k0 + lrow) * ATS + nj * 16 + lcol) * 2);
            #pragma unroll
            for (int nj = 0; nj < 4; ++nj) {
                uint32_t f1[2] = {bfr[nj][0], bfr[nj][2]};
                uint32_t f2[2] = {bfr[nj][1], bfr[nj][3]};
                mma16816(acc[nj * 2],     a, f1);
                mma16816(acc[nj * 2 + 1], a, f2);
            }
            mma16816(acce, a, onesf);
        }
        __syncthreads();
    }

    int gr = lane >> 2, gc = (lane & 3) * 2;
    int r = r0 + m0 + gr;
    #pragma unroll
    for (int nj = 0; nj < 8; ++nj) {
        int w = nj * 8 + gc;
        *(float2*)&g_add[(size_t)r * NW + w]       = make_float2(acc[nj][0], acc[nj][1]);
        *(float2*)&g_add[(size_t)(r + 8) * NW + w] = make_float2(acc[nj][2], acc[nj][3]);
    }
    if ((lane & 3) == 0) { g_er[r] = acce[0]; g_er[r + 8] = acce[2]; }
}

// ---------------- K4b: mem2 = mem*(1-er/B) + add/B, transpose + bf16 hi/lo ----------
__global__ void mem2t_kernel(const float* __restrict__ mem) {
    __shared__ float t[64][65];
    __shared__ float ev[64];
    int r0 = blockIdx.x * 64;
    int tid = threadIdx.x;
    const float invB = 1.f / (float)NB;

    if (tid < 64) ev[tid] = 1.f - g_er[r0 + tid] * invB;
    __syncthreads();

    #pragma unroll
    for (int i = 0; i < 16; ++i) {
        int q = tid + i * 256;
        int r = q >> 6, w = q & 63;
        t[r][w] = mem[(size_t)(r0 + r) * NW + w] * ev[r] + g_add[(size_t)(r0 + r) * NW + w] * invB;
    }
    __syncthreads();

    #pragma unroll
    for (int i = 0; i < 16; ++i) {
        int q = tid + i * 256;
        int w = q >> 6, r = q & 63;
        float f = t[r][w];
        __nv_bfloat16 h = __float2bfloat16(f);
        __nv_bfloat16 l = __float2bfloat16(f - __bfloat162float(h));
        g_m2h[(size_t)w * NR + r0 + r] = h;
        g_m2l[(size_t)w * NR + r0 + r] = l;
    }
}

// ---------------- prep: xcat = [x_hi | x_lo | x_hi] ----------------
__global__ void xcat_kernel(const float* __restrict__ x) {
    int i = blockIdx.x * 256 + threadIdx.x;
    int b = i >> 8, k = i & 255;
    float f = x[i];
    __nv_bfloat16 h = __float2bfloat16(f);
    __nv_bfloat16 l = __float2bfloat16(f - __bfloat162float(h));
    g_xcat[(size_t)b * KCAT + k]       = h;
    g_xcat[(size_t)b * KCAT + 256 + k] = l;
    g_xcat[(size_t)b * KCAT + 512 + k] = h;
}

// ---------------- prep: wcat ----------------
__global__ void wcat_kernel(const float* __restrict__ Wp) {
    __shared__ float t[32][33];
    int n0 = blockIdx.x * 32, k0 = blockIdx.y * 32;
    int tx = threadIdx.x, ty = threadIdx.y;   // (32, 8)
    #pragma unroll
    for (int i = 0; i < 4; ++i)
        t[ty + 8 * i][tx] = Wp[(size_t)(k0 + ty + 8 * i) * NR + n0 + tx];
    __syncthreads();
    #pragma unroll
    for (int i = 0; i < 4; ++i) {
        int row = ty + 8 * i;
        float f = t[tx][row];
        __nv_bfloat16 h = __float2bfloat16(f);
        __nv_bfloat16 l = __float2bfloat16(f - __bfloat162float(h));
        size_t base = (size_t)(n0 + row) * KCAT + k0 + tx;
        g_wcat[base]       = h;
        g_wcat[base + 256] = h;
        g_wcat[base + 512] = l;
    }
}

// ---------------- K5: p logits, 128x256 CTA tile, cp.async 3-stage ----------------
#define PLS 40
#define PLK (KCAT / 32)
#define PL_ABUF (128 * PLS)
#define PL_BBUF (256 * PLS)

__global__ void __launch_bounds__(512, 1)
pl_mma_kernel(const float* __restrict__ bp) {
    extern __shared__ __nv_bfloat16 sm[];
    __nv_bfloat16* As = sm;                       // [3][128][PLS]
    __nv_bfloat16* Bs = sm + 3 * PL_ABUF;         // [3][256][PLS]
    int tid = threadIdx.x;
    int lane = tid & 31, wid = tid >> 5;          // 16 warps
    int n0 = blockIdx.x * 256;
    int b0 = blockIdx.y * 128;
    int wm0 = (wid & 3) * 32;
    int wn0 = (wid >> 2) * 64;

    uint32_t asb = smem_u32(As), bsb = smem_u32(Bs);
    const uint32_t abufB = PL_ABUF * 2, bbufB = PL_BBUF * 2;

    int arow = tid >> 2, aseg = (tid & 3) * 8;
    int brow0 = tid >> 2, bseg0 = (tid & 3) * 8;
    int brow1 = (tid + 512) >> 2, bseg1 = (tid & 3) * 8;

    uint32_t a_sa  = asb + (arow * PLS + aseg) * 2;
    uint32_t b_sa0 = bsb + (brow0 * PLS + bseg0) * 2;
    uint32_t b_sa1 = bsb + (brow1 * PLS + bseg1) * 2;
    const __nv_bfloat16* a_g  = &g_xcat[(size_t)(b0 + arow) * KCAT + aseg];
    const __nv_bfloat16* b_g0 = &g_wcat[(size_t)(n0 + brow0) * KCAT + bseg0];
    const __nv_bfloat16* b_g1 = &g_wcat[(size_t)(n0 + brow1) * KCAT + bseg1];

    // prologue: stages 0, 1
    #pragma unroll
    for (int s = 0; s < 2; ++s) {
        cp_async16(a_sa + s * abufB, a_g + s * 32);
        cp_async16(b_sa0 + s * bbufB, b_g0 + s * 32);
        cp_async16(b_sa1 + s * bbufB, b_g1 + s * 32);
        CP_COMMIT();
    }

    float acc[2][8][4] = {};
    int a_row = wm0 + (lane & 15);
    int a_kof = (lane >> 4) * 8;
    int b_rof = ((lane >> 4) * 8) + (lane & 7);
    int b_kof = ((lane >> 3) & 1) * 8;

    for (int kc = 0; kc < PLK; ++kc) {
        int cur = kc % 3;
        if (kc + 2 < PLK) {
            int nxt = (kc + 2) % 3;
            int ko = (kc + 2) * 32;
            cp_async16(a_sa + nxt * abufB, a_g + ko);
            cp_async16(b_sa0 + nxt * bbufB, b_g0 + ko);
            cp_async16(b_sa1 + nxt * bbufB, b_g1 + ko);
            CP_COMMIT();
            CP_WAIT(2);
        } else if (kc + 1 < PLK) {
            CP_WAIT(1);
        } else {
            CP_WAIT(0);
        }
        __syncthreads();

        uint32_t abase = asb + cur * abufB;
        uint32_t bbase = bsb + cur * bbufB;
        #pragma unroll
        for (int ks = 0; ks < 2; ++ks) {
            int k0 = ks * 16;
            uint32_t a[2][4];
            #pragma unroll
            for (int mi = 0; mi < 2; ++mi) {
                uint32_t addr = abase + ((a_row + mi * 16) * PLS + k0 + a_kof) * 2;
                ldsm_x4(a[mi][0], a[mi][1], a[mi][2], a[mi][3], addr);
            }
            uint32_t bfr[4][4];
            #pragma unroll
            for (int nj = 0; nj < 4; ++nj) {
                uint32_t addr = bbase + ((wn0 + nj * 16 + b_rof) * PLS + k0 + b_kof) * 2;
                ldsm_x4(bfr[nj][0], bfr[nj][1], bfr[nj][2], bfr[nj][3], addr);
            }
            #pragma unroll
            for (int mi = 0; mi < 2; ++mi)
                #pragma unroll
                for (int nj = 0; nj < 4; ++nj) {
                    mma16816(acc[mi][nj * 2],     a[mi], &bfr[nj][0]);
                    mma16816(acc[mi][nj * 2 + 1], a[mi], &bfr[nj][2]);
                }
        }
        __syncthreads();
    }

    int gr = lane >> 2, gc = (lane & 3) * 2;
    #pragma unroll
    for (int mi = 0; mi < 2; ++mi) {
        int r1 = b0 + wm0 + mi * 16 + gr;
        #pragma unroll
        for (int j = 0; j < 8; ++j) {
            int c = n0 + wn0 + j * 8 + gc;
            float bpx = bp[c], bpy = bp[c + 1];
            *(float2*)&g_pl[(size_t)r1 * NR + c] =
                make_float2(acc[mi][j][0] + bpx, acc[mi][j][1] + bpy);
            *(float2*)&g_pl[(size_t)(r1 + 8) * NR + c] =
                make_float2(acc[mi][j][2] + bpx, acc[mi][j][3] + bpy);
        }
    }
}

// ---------------- K6: per-row softmax stats for p (float4) ----------------
__global__ void pstats_kernel() {
    __shared__ float red[32];
    int b = blockIdx.x, t = threadIdx.x;
    const float* row = g_pl + (size_t)b * NR;

    float4 loc[4];
    float mx = -1e30f;
    #pragma unroll
    for (int i = 0; i < 4; ++i) {
        loc[i] = *(const float4*)&row[i * 4096 + t * 4];
        mx = fmaxf(mx, fmaxf(fmaxf(loc[i].x, loc[i].y), fmaxf(loc[i].z, loc[i].w)));
    }
    mx = blk_max(mx, red);

    float sum = 0.f;
    #pragma unroll
    for (int i = 0; i < 4; ++i)
        sum += __expf(loc[i].x - mx) + __expf(loc[i].y - mx)
             + __expf(loc[i].z - mx) + __expf(loc[i].w - mx);
    sum = blk_sum(sum, red);

    if (t == 0) { g_pmx[b] = mx; g_pinv[b] = 1.f / sum; }
}

// ---------------- K7: out = softmax(pl) @ mem2 via HMMA hi/lo split ----------------
#define OLS 72
#define O_EH 0
#define O_EL (128 * OLS)
#define O_MH (256 * OLS)
#define O_ML (320 * OLS)
#define O_SMEM (384 * OLS * 2)

__global__ void __launch_bounds__(256, 2)
out_tc_kernel() {
    extern __shared__ __nv_bfloat16 osm[];
    __nv_bfloat16* EH = osm + O_EH;
    __nv_bfloat16* EL = osm + O_EL;
    __nv_bfloat16* MH = osm + O_MH;
    __nv_bfloat16* ML = osm + O_ML;
    int tid = threadIdx.x;
    int lane = tid & 31, wid = tid >> 5;
    int split = blockIdx.x;
    int b0 = blockIdx.y * 128;
    int kbase = split * (NR / NSPLIT);

    int la = tid >> 4, lb = tid & 15;
    float mxv[8], invv[8];
    #pragma unroll
    for (int i = 0; i < 8; ++i) {
        mxv[i]  = g_pmx[b0 + la + 16 * i];
        invv[i] = g_pinv[b0 + la + 16 * i];
    }
    int m_row0 = tid >> 3, m_seg0 = (tid & 7) * 8;
    int m_row1 = (tid + 256) >> 3, m_seg1 = (tid & 7) * 8;

    uint32_t ehb = smem_u32(EH), elb = smem_u32(EL);
    uint32_t mhb = smem_u32(MH), mlb = smem_u32(ML);

    float acc[8][4] = {};
    int a_row = wid * 16 + (lane & 15);
    int a_kof = (lane >> 4) * 8;
    int b_rof = ((lane >> 4) * 8) + (lane & 7);
    int b_kof = ((lane >> 3) & 1) * 8;

    for (int kg = kbase; kg < kbase + NR / NSPLIT; kg += 64) {
        #pragma unroll
        for (int i = 0; i < 8; ++i) {
            int row = la + 16 * i;
            float4 l4 = *(const float4*)&g_pl[(size_t)(b0 + row) * NR + kg + lb * 4];
            float e0 = __expf(l4.x - mxv[i]) * invv[i];
            float e1 = __expf(l4.y - mxv[i]) * invv[i];
            float e2 = __expf(l4.z - mxv[i]) * invv[i];
            float e3 = __expf(l4.w - mxv[i]) * invv[i];
            __nv_bfloat16 h0 = __float2bfloat16(e0), h1 = __float2bfloat16(e1);
            __nv_bfloat16 h2 = __float2bfloat16(e2), h3 = __float2bfloat16(e3);
            __nv_bfloat16 l0 = __float2bfloat16(e0 - __bfloat162float(h0));
            __nv_bfloat16 l1 = __float2bfloat16(e1 - __bfloat162float(h1));
            __nv_bfloat16 l2 = __float2bfloat16(e2 - __bfloat162float(h2));
            __nv_bfloat16 l3 = __float2bfloat16(e3 - __bfloat162float(h3));
            __nv_bfloat16* eh = &EH[row * OLS + lb * 4];
            __nv_bfloat16* el = &EL[row * OLS + lb * 4];
            eh[0] = h0; eh[1] = h1; eh[2] = h2; eh[3] = h3;
            el[0] = l0; el[1] = l1; el[2] = l2; el[3] = l3;
        }
        *(uint4*)&MH[m_row0 * OLS + m_seg0] = *(const uint4*)&g_m2h[(size_t)m_row0 * NR + kg + m_seg0];
        *(uint4*)&MH[m_row1 * OLS + m_seg1] = *(const uint4*)&g_m2h[(size_t)m_row1 * NR + kg + m_seg1];
        *(uint4*)&ML[m_row0 * OLS + m_seg0] = *(const uint4*)&g_m2l[(size_t)m_row0 * NR + kg + m_seg0];
        *(uint4*)&ML[m_row1 * OLS + m_seg1] = *(const uint4*)&g_m2l[(size_t)m_row1 * NR + kg + m_seg1];
        __syncthreads();

        #pragma unroll
        for (int ks = 0; ks < 4; ++ks) {
            int k0 = ks * 16;
            uint32_t ah[4], al[4];
            {
                uint32_t addr = ehb + (a_row * OLS + k0 + a_kof) * 2;
                ldsm_x4(ah[0], ah[1], ah[2], ah[3], addr);
                addr = elb + (a_row * OLS + k0 + a_kof) * 2;
                ldsm_x4(al[0], al[1], al[2], al[3], addr);
            }
            uint32_t bh[4][4], bl[4][4];
            #pragma unroll
            for (int g = 0; g < 4; ++g) {
                uint32_t addr = mhb + ((g * 16 + b_rof) * OLS + k0 + b_kof) * 2;
                ldsm_x4(bh[g][0], bh[g][1], bh[g][2], bh[g][3], addr);
                addr = mlb + ((g * 16 + b_rof) * OLS + k0 + b_kof) * 2;
                ldsm_x4(bl[g][0], bl[g][1], bl[g][2], bl[g][3], addr);
            }
            #pragma unroll
            for (int g = 0; g < 4; ++g) {
                mma16816(acc[g * 2],     ah, &bh[g][0]);
                mma16816(acc[g * 2 + 1], ah, &bh[g][2]);
                mma16816(acc[g * 2],     al, &bh[g][0]);
                mma16816(acc[g * 2 + 1], al, &bh[g][2]);
                mma16816(acc[g * 2],     ah, &bl[g][0]);
                mma16816(acc[g * 2 + 1], ah, &bl[g][2]);
            }
        }
        __syncthreads();
    }

    int gr = lane >> 2, gc = (lane & 3) * 2;
    int r1 = b0 + wid * 16 + gr;
    #pragma unroll
    for (int j = 0; j < 8; ++j) {
        int c = j * 8 + gc;
        *(float2*)&g_part[(size_t)split * (NB * NW) + (size_t)r1 * NW + c] =
            make_float2(acc[j][0], acc[j][1]);
        *(float2*)&g_part[(size_t)split * (NB * NW) + (size_t)(r1 + 8) * NW + c] =
            make_float2(acc[j][2], acc[j][3]);
    }
}

__global__ void out_reduce(float* __restrict__ out) {
    int i = blockIdx.x * blockDim.x + threadIdx.x;
    float s = 0.f;
    #pragma unroll
    for (int p = 0; p < NSPLIT; ++p) s += g_part[(size_t)p * (NB * NW) + i];
    out[i] = s;
}

// ---------------- launch ----------------
extern "C" void kernel_launch(void* const* d_in, const int* in_sizes, int n_in,
                              void* d_out, int out_size) {
    const float* x   = (const float*)d_in[0];
    const float* Wv  = (const float*)d_in[1];
    const float* bv  = (const float*)d_in[2];
    const float* Wb  = (const float*)d_in[3];
    const float* bb  = (const float*)d_in[4];
    const float* Wg  = (const float*)d_in[5];
    const float* bg  = (const float*)d_in[6];
    const float* Wp  = (const float*)d_in[7];
    const float* bp  = (const float*)d_in[8];
    const float* ck  = (const float*)d_in[9];
    const float* cbv = (const float*)d_in[10];
    const float* mem = (const float*)d_in[11];
    float* out = (float*)d_out;
    (void)in_sizes; (void)n_in; (void)out_size;

    const int pl_smem = 3 * (PL_ABUF + PL_BBUF) * 2;
    cudaFuncSetAttribute(wa_kernel, cudaFuncAttributeMaxDynamicSharedMemorySize, NR * 4);
    cudaFuncSetAttribute(pl_mma_kernel, cudaFuncAttributeMaxDynamicSharedMemorySize, pl_smem);
    cudaFuncSetAttribute(out_tc_kernel, cudaFuncAttributeMaxDynamicSharedMemorySize, O_SMEM);

    // order chosen so pl_mma_kernel is launch index 3 (ncu capture slot)
    xcat_kernel<<<NB * ND / 256, 256>>>(x);
    wcat_kernel<<<dim3(NR / 32, ND / 32), dim3(32, 8)>>>(Wp);
    heads_kernel<<<NB, 64>>>(x, Wv, bv, Wb, bb, Wg, bg);
    pl_mma_kernel<<<dim3(NR / 256, NB / 128), 512, pl_smem>>>(bp);
    mn_kernel<<<NR / 256, 256>>>(mem);
    memh_kernel<<<NR * NW / 4 / 256, 256>>>(mem);
    sim_tc_kernel<<<dim3(NR / 128, NB / 128), 256>>>();
    wa_kernel<<<NB, 1024, NR * 4>>>(ck, cbv);
    add_tc_kernel<<<NR / 64, 128>>>();
    mem2t_kernel<<<NR / 64, 256>>>(mem);
    pstats_kernel<<<NB, 1024>>>();
    out_tc_kernel<<<dim3(NSPLIT, NB / 128), 256, O_SMEM>>>();
    out_reduce<<<NB * NW / 256, 256>>>(out);
}